// round 2
// baseline (speedup 1.0000x reference)
#include <cuda_runtime.h>
#include <math.h>
#include <stdint.h>

// Problem constants
#define D_    512
#define S_    512
#define B_    4
#define H_    8
#define L_    6
#define DFF_  2048
#define V_    32000
#define BS_   (B_ * S_)
#define NEGV  (-1e10f)

// ---------------------------------------------------------------------------
// Scratch (device globals; no allocation allowed)
// ---------------------------------------------------------------------------
__device__ float g_x[BS_ * D_];      // encoder state / final enc
__device__ float g_q[BS_ * D_];
__device__ float g_k[BS_ * D_];
__device__ float g_v[BS_ * D_];
__device__ float g_attn[BS_ * D_];
__device__ float g_a[BS_ * D_];
__device__ float g_out[BS_ * D_];
__device__ float g_h[BS_ * DFF_];
__device__ float g_f[BS_ * D_];
__device__ float g_y0[BS_ * D_];
__device__ float g_o[BS_ * D_];

// ---------------------------------------------------------------------------
// Embedding + sinusoidal positional encoding
// out[row, d] = emb[ids[row], d] + pe(row % S, d)
// ---------------------------------------------------------------------------
__global__ __launch_bounds__(128) void embed_kernel(
    const int* __restrict__ ids, const float* __restrict__ emb,
    float* __restrict__ out)
{
    const int row = blockIdx.x;          // 0..BS_-1
    const int s   = row & (S_ - 1);
    const int tok = ids[row];
    const int t   = threadIdx.x;
    const float c = -logf(10000.0f) / (float)D_;
    #pragma unroll
    for (int j = 0; j < 4; j++) {
        int d  = t * 4 + j;
        int tj = d >> 1;
        float div = expf((float)(2 * tj) * c);
        float ang = (float)s * div;
        float pe  = (d & 1) ? cosf(ang) : sinf(ang);
        out[(size_t)row * D_ + d] = emb[(size_t)tok * D_ + d] + pe;
    }
}

// ---------------------------------------------------------------------------
// Fused residual-add + LayerNorm (no affine): Out = LN(A + Bv) per row of 512
// Safe in-place (each block reads its full row into registers before writing)
// ---------------------------------------------------------------------------
__global__ __launch_bounds__(128) void add_ln_kernel(
    const float* __restrict__ A, const float* __restrict__ Bv,
    float* __restrict__ Out)
{
    const int row = blockIdx.x;
    const int t   = threadIdx.x;
    const size_t base = (size_t)row * D_ + t * 4;
    float4 a = *(const float4*)(A + base);
    float4 b = *(const float4*)(Bv + base);
    float4 vv;
    vv.x = a.x + b.x; vv.y = a.y + b.y; vv.z = a.z + b.z; vv.w = a.w + b.w;

    float s  = vv.x + vv.y + vv.z + vv.w;
    float sq = vv.x * vv.x + vv.y * vv.y + vv.z * vv.z + vv.w * vv.w;

    __shared__ float redS[4], redQ[4];
    #pragma unroll
    for (int off = 16; off > 0; off >>= 1) {
        s  += __shfl_xor_sync(0xffffffffu, s,  off);
        sq += __shfl_xor_sync(0xffffffffu, sq, off);
    }
    const int wid = t >> 5, lane = t & 31;
    if (lane == 0) { redS[wid] = s; redQ[wid] = sq; }
    __syncthreads();
    s  = redS[0] + redS[1] + redS[2] + redS[3];
    sq = redQ[0] + redQ[1] + redQ[2] + redQ[3];

    float mean = s * (1.0f / D_);
    float var  = sq * (1.0f / D_) - mean * mean;
    float inv  = rsqrtf(var + 1e-5f);

    float4 o;
    o.x = (vv.x - mean) * inv; o.y = (vv.y - mean) * inv;
    o.z = (vv.z - mean) * inv; o.w = (vv.w - mean) * inv;
    *(float4*)(Out + base) = o;
}

// ---------------------------------------------------------------------------
// SGEMM: C[M,N] = A[M,K] @ B[K,N]  (row-major), EPI: 0 none, 1 +bias, 2 +bias+relu
// BM=128, BN=64, BK=16, 256 threads, 8x4 per-thread microtile.
// Requires: M%128==0, N%64==0, K%16==0 (true for all shapes here).
// ---------------------------------------------------------------------------
template<int EPI>
__global__ __launch_bounds__(256) void sgemm_kernel(
    const float* __restrict__ A, const float* __restrict__ B,
    const float* __restrict__ bias, float* __restrict__ C,
    int M, int N, int K)
{
    __shared__ float As[16][132];   // transposed A tile: As[k][m]
    __shared__ float Bs[16][64];    // Bs[k][n]

    const int tid  = threadIdx.x;
    const int bm   = blockIdx.y * 128;
    const int bn   = blockIdx.x * 64;
    const int ty   = tid >> 4;      // 0..15
    const int tx   = tid & 15;      // 0..15
    const int row0 = ty * 8;
    const int col0 = tx * 4;

    float acc[8][4];
    #pragma unroll
    for (int i = 0; i < 8; i++)
        #pragma unroll
        for (int j = 0; j < 4; j++) acc[i][j] = 0.0f;

    for (int k0 = 0; k0 < K; k0 += 16) {
        // Load A tile (128x16) transposed into As
        #pragma unroll
        for (int tt = 0; tt < 2; tt++) {
            int idx = tid + tt * 256;           // 0..511
            int r   = idx >> 2;                 // 0..127
            int c4  = (idx & 3) * 4;            // 0,4,8,12
            float4 av = *(const float4*)(A + (size_t)(bm + r) * K + k0 + c4);
            As[c4 + 0][r] = av.x;
            As[c4 + 1][r] = av.y;
            As[c4 + 2][r] = av.z;
            As[c4 + 3][r] = av.w;
        }
        // Load B tile (16x64)
        {
            int r  = tid >> 4;                  // 0..15
            int c4 = (tid & 15) * 4;            // 0..60
            *(float4*)&Bs[r][c4] =
                *(const float4*)(B + (size_t)(k0 + r) * N + bn + c4);
        }
        __syncthreads();

        #pragma unroll
        for (int kk = 0; kk < 16; kk++) {
            float4 a0 = *(const float4*)&As[kk][row0];
            float4 a1 = *(const float4*)&As[kk][row0 + 4];
            float4 bv = *(const float4*)&Bs[kk][col0];
            float aa[8] = {a0.x, a0.y, a0.z, a0.w, a1.x, a1.y, a1.z, a1.w};
            float bb[4] = {bv.x, bv.y, bv.z, bv.w};
            #pragma unroll
            for (int i = 0; i < 8; i++)
                #pragma unroll
                for (int j = 0; j < 4; j++)
                    acc[i][j] += aa[i] * bb[j];
        }
        __syncthreads();
    }

    float4 bvec = make_float4(0.f, 0.f, 0.f, 0.f);
    if (EPI >= 1) bvec = *(const float4*)(bias + bn + col0);

    #pragma unroll
    for (int i = 0; i < 8; i++) {
        float4 r;
        r.x = acc[i][0] + bvec.x;
        r.y = acc[i][1] + bvec.y;
        r.z = acc[i][2] + bvec.z;
        r.w = acc[i][3] + bvec.w;
        if (EPI == 2) {
            r.x = fmaxf(r.x, 0.f); r.y = fmaxf(r.y, 0.f);
            r.z = fmaxf(r.z, 0.f); r.w = fmaxf(r.w, 0.f);
        }
        *(float4*)(C + (size_t)(bm + row0 + i) * N + bn + col0) = r;
    }
}

// ---------------------------------------------------------------------------
// Fused attention (flash-style, online softmax).
// Layout: Q,K,V,O are [B, S, D] with head h occupying cols [h*64, h*64+64).
// Grid: (S/16, H, B), 128 threads. KV length = S (both self and cross).
// score = qk/8 + (kv_tok==0 ? NEG : 0) + (causal && k>q ? NEG : 0)
// ---------------------------------------------------------------------------
__global__ __launch_bounds__(128) void attn_kernel(
    const float* __restrict__ Q, const float* __restrict__ Km,
    const float* __restrict__ Vm, const int* __restrict__ kv_tok,
    float* __restrict__ O, int causal)
{
    __shared__ float4 Qs[16][16];       // Qs[qi][d4]
    __shared__ float4 Buf[128 * 17];    // K or V tile, row pitch 17 float4
    __shared__ float  Ssc[16][128];     // scores/probs for current 128 keys
    __shared__ float  mstat[16], lstat[16], corrS[16];

    const int t  = threadIdx.x;
    const int qt = blockIdx.x, h = blockIdx.y, b = blockIdx.z;
    const int q0g = qt * 16;
    const size_t hcol = (size_t)h * 64;

    // Load Q tile
    {
        const size_t baseQ = ((size_t)(b * S_ + q0g)) * D_ + hcol;
        #pragma unroll
        for (int it = 0; it < 2; it++) {
            int idx = t + it * 128;
            int r = idx >> 4, c4 = idx & 15;
            Qs[r][c4] = *(const float4*)(Q + baseQ + (size_t)r * D_ + c4 * 4);
        }
    }
    if (t < 16) { mstat[t] = -1e30f; lstat[t] = 0.f; }

    float4 oa0 = make_float4(0.f, 0.f, 0.f, 0.f);
    float4 oa1 = make_float4(0.f, 0.f, 0.f, 0.f);
    const int qiA = (t >> 4) * 2;   // AV: 2 rows per thread
    const int dA  = (t & 15);       // AV: float4 column
    const int qiS = (t >> 5);       // scores: base qi (+4*qq)
    const int kjS = (t & 31);       // scores: base kj (+32*kk)

    for (int kb = 0; kb < 4; kb++) {
        __syncthreads();
        // --- Load K tile (128 keys x 64 dims) ---
        {
            const size_t baseK = ((size_t)(b * S_ + kb * 128)) * D_ + hcol;
            #pragma unroll
            for (int it = 0; it < 16; it++) {
                int idx = t + it * 128;
                int r = idx >> 4, c4 = idx & 15;
                Buf[r * 17 + c4] =
                    *(const float4*)(Km + baseK + (size_t)r * D_ + c4 * 4);
            }
        }
        __syncthreads();
        // --- Scores: each thread 4 qi x 4 kj ---
        {
            float acc[4][4];
            #pragma unroll
            for (int qq = 0; qq < 4; qq++)
                #pragma unroll
                for (int kk = 0; kk < 4; kk++) acc[qq][kk] = 0.f;
            #pragma unroll
            for (int d4 = 0; d4 < 16; d4++) {
                float4 kv[4];
                #pragma unroll
                for (int kk = 0; kk < 4; kk++)
                    kv[kk] = Buf[(kjS + 32 * kk) * 17 + d4];
                #pragma unroll
                for (int qq = 0; qq < 4; qq++) {
                    float4 qv = Qs[qiS + 4 * qq][d4];
                    #pragma unroll
                    for (int kk = 0; kk < 4; kk++) {
                        acc[qq][kk] += qv.x * kv[kk].x + qv.y * kv[kk].y
                                     + qv.z * kv[kk].z + qv.w * kv[kk].w;
                    }
                }
            }
            #pragma unroll
            for (int qq = 0; qq < 4; qq++) {
                int qi = qiS + 4 * qq;
                int qg = q0g + qi;
                #pragma unroll
                for (int kk = 0; kk < 4; kk++) {
                    int kj = kjS + 32 * kk;
                    int kg = kb * 128 + kj;
                    float s = acc[qq][kk] * 0.125f;  // 1/sqrt(64)
                    if (kv_tok[b * S_ + kg] == 0) s += NEGV;
                    if (causal && kg > qg) s += NEGV;
                    Ssc[qi][kj] = s;
                }
            }
        }
        __syncthreads();
        // --- Online softmax stats: 8 lanes per row ---
        {
            int row = t >> 3, l8 = t & 7;
            float mloc = -1e30f;
            #pragma unroll
            for (int c = 0; c < 16; c++)
                mloc = fmaxf(mloc, Ssc[row][l8 + 8 * c]);
            #pragma unroll
            for (int off = 4; off > 0; off >>= 1)
                mloc = fmaxf(mloc, __shfl_xor_sync(0xffffffffu, mloc, off));
            float m_old = mstat[row];
            float m_new = fmaxf(m_old, mloc);
            float ssum = 0.f;
            #pragma unroll
            for (int c = 0; c < 16; c++) {
                float p = expf(Ssc[row][l8 + 8 * c] - m_new);
                Ssc[row][l8 + 8 * c] = p;
                ssum += p;
            }
            #pragma unroll
            for (int off = 4; off > 0; off >>= 1)
                ssum += __shfl_xor_sync(0xffffffffu, ssum, off);
            if (l8 == 0) {
                float corr = expf(m_old - m_new);
                corrS[row] = corr;
                lstat[row] = lstat[row] * corr + ssum;
                mstat[row] = m_new;
            }
        }
        __syncthreads();
        // --- Load V tile (reuse Buf) ---
        {
            const size_t baseV = ((size_t)(b * S_ + kb * 128)) * D_ + hcol;
            #pragma unroll
            for (int it = 0; it < 16; it++) {
                int idx = t + it * 128;
                int r = idx >> 4, c4 = idx & 15;
                Buf[r * 17 + c4] =
                    *(const float4*)(Vm + baseV + (size_t)r * D_ + c4 * 4);
            }
        }
        __syncthreads();
        // --- AV accumulate ---
        {
            float c0 = corrS[qiA], c1 = corrS[qiA + 1];
            oa0.x *= c0; oa0.y *= c0; oa0.z *= c0; oa0.w *= c0;
            oa1.x *= c1; oa1.y *= c1; oa1.z *= c1; oa1.w *= c1;
            #pragma unroll 4
            for (int kj = 0; kj < 128; kj++) {
                float p0 = Ssc[qiA][kj];
                float p1 = Ssc[qiA + 1][kj];
                float4 vv = Buf[kj * 17 + dA];
                oa0.x += p0 * vv.x; oa0.y += p0 * vv.y;
                oa0.z += p0 * vv.z; oa0.w += p0 * vv.w;
                oa1.x += p1 * vv.x; oa1.y += p1 * vv.y;
                oa1.z += p1 * vv.z; oa1.w += p1 * vv.w;
            }
        }
    }
    __syncthreads();
    // --- Write out ---
    {
        float inv0 = 1.f / lstat[qiA];
        float inv1 = 1.f / lstat[qiA + 1];
        float4 r0 = make_float4(oa0.x * inv0, oa0.y * inv0, oa0.z * inv0, oa0.w * inv0);
        float4 r1 = make_float4(oa1.x * inv1, oa1.y * inv1, oa1.z * inv1, oa1.w * inv1);
        size_t base0 = ((size_t)(b * S_ + q0g + qiA)) * D_ + hcol + dA * 4;
        size_t base1 = ((size_t)(b * S_ + q0g + qiA + 1)) * D_ + hcol + dA * 4;
        *(float4*)(O + base0) = r0;
        *(float4*)(O + base1) = r1;
    }
}

// ---------------------------------------------------------------------------
// Host driver
// ---------------------------------------------------------------------------
static inline void run_gemm(const float* A, const float* Bm, const float* bias,
                            float* C, int M, int N, int K, int epi)
{
    dim3 grid(N / 64, M / 128);
    if (epi == 0)      sgemm_kernel<0><<<grid, 256>>>(A, Bm, nullptr, C, M, N, K);
    else if (epi == 1) sgemm_kernel<1><<<grid, 256>>>(A, Bm, bias, C, M, N, K);
    else               sgemm_kernel<2><<<grid, 256>>>(A, Bm, bias, C, M, N, K);
}

extern "C" void kernel_launch(void* const* d_in, const int* in_sizes, int n_in,
                              void* d_out, int out_size)
{
    const int DD  = D_ * D_;
    const int DDF = D_ * DFF_;

    // Resolve input ordering by size fingerprint at index 7:
    //   setup_inputs order  -> in_sizes[7] == L*D*D       (dec_Wq1)
    //   reference-arg order -> in_sizes[7] == L*D*DFF     (enc_W1)
    int iEWq, iEWk, iEWv, iEWo, iEW1, iEb1, iEW2, iEb2;
    int iDWq1, iDWk1, iDWv1, iDWo1, iDWq2, iDWk2, iDWv2, iDWo2;
    int iDW1, iDb1, iDW2, iDb2, iWout, iBout;
    if (n_in >= 8 && in_sizes[7] == L_ * DD) {
        iEWq = 3; iEWk = 4; iEWv = 5; iEWo = 6;
        iDWq1 = 7; iDWk1 = 8; iDWv1 = 9; iDWo1 = 10;
        iDWq2 = 11; iDWk2 = 12; iDWv2 = 13; iDWo2 = 14;
        iEW1 = 15; iEb1 = 16; iEW2 = 17; iEb2 = 18;
        iDW1 = 19; iDb1 = 20; iDW2 = 21; iDb2 = 22;
        iWout = 23; iBout = 24;
    } else {
        iEWq = 3; iEWk = 4; iEWv = 5; iEWo = 6;
        iEW1 = 7; iEb1 = 8; iEW2 = 9; iEb2 = 10;
        iDWq1 = 11; iDWk1 = 12; iDWv1 = 13; iDWo1 = 14;
        iDWq2 = 15; iDWk2 = 16; iDWv2 = 17; iDWo2 = 18;
        iDW1 = 19; iDb1 = 20; iDW2 = 21; iDb2 = 22;
        iWout = 23; iBout = 24;
    }

    const int*   src  = (const int*)d_in[0];
    const int*   tgt  = (const int*)d_in[1];
    const float* emb  = (const float*)d_in[2];
    const float* eWq  = (const float*)d_in[iEWq];
    const float* eWk  = (const float*)d_in[iEWk];
    const float* eWv  = (const float*)d_in[iEWv];
    const float* eWo  = (const float*)d_in[iEWo];
    const float* eW1  = (const float*)d_in[iEW1];
    const float* eb1  = (const float*)d_in[iEb1];
    const float* eW2  = (const float*)d_in[iEW2];
    const float* eb2  = (const float*)d_in[iEb2];
    const float* dWq1 = (const float*)d_in[iDWq1];
    const float* dWk1 = (const float*)d_in[iDWk1];
    const float* dWv1 = (const float*)d_in[iDWv1];
    const float* dWo1 = (const float*)d_in[iDWo1];
    const float* dWq2 = (const float*)d_in[iDWq2];
    const float* dWk2 = (const float*)d_in[iDWk2];
    const float* dWv2 = (const float*)d_in[iDWv2];
    const float* dWo2 = (const float*)d_in[iDWo2];
    const float* dW1  = (const float*)d_in[iDW1];
    const float* db1  = (const float*)d_in[iDb1];
    const float* dW2  = (const float*)d_in[iDW2];
    const float* db2  = (const float*)d_in[iDb2];
    const float* Wout = (const float*)d_in[iWout];
    const float* bout = (const float*)d_in[iBout];

    float *x, *q, *k, *v, *attn, *a, *out, *hbuf, *f, *y0, *o;
    cudaGetSymbolAddress((void**)&x,    g_x);
    cudaGetSymbolAddress((void**)&q,    g_q);
    cudaGetSymbolAddress((void**)&k,    g_k);
    cudaGetSymbolAddress((void**)&v,    g_v);
    cudaGetSymbolAddress((void**)&attn, g_attn);
    cudaGetSymbolAddress((void**)&a,    g_a);
    cudaGetSymbolAddress((void**)&out,  g_out);
    cudaGetSymbolAddress((void**)&hbuf, g_h);
    cudaGetSymbolAddress((void**)&f,    g_f);
    cudaGetSymbolAddress((void**)&y0,   g_y0);
    cudaGetSymbolAddress((void**)&o,    g_o);

    const dim3 attnGrid(S_ / 16, H_, B_);

    // ---------------- Encoder ----------------
    embed_kernel<<<BS_, 128>>>(src, emb, x);
    for (int i = 0; i < L_; i++) {
        run_gemm(x, eWq + (size_t)i * DD, nullptr, q, BS_, D_, D_, 0);
        run_gemm(x, eWk + (size_t)i * DD, nullptr, k, BS_, D_, D_, 0);
        run_gemm(x, eWv + (size_t)i * DD, nullptr, v, BS_, D_, D_, 0);
        attn_kernel<<<attnGrid, 128>>>(q, k, v, src, attn, 0);
        run_gemm(attn, eWo + (size_t)i * DD, nullptr, a, BS_, D_, D_, 0);
        add_ln_kernel<<<BS_, 128>>>(x, a, out);                      // out = LN(x+a)
        run_gemm(out, eW1 + (size_t)i * DDF, eb1 + (size_t)i * DFF_, hbuf,
                 BS_, DFF_, D_, 2);                                   // relu
        run_gemm(hbuf, eW2 + (size_t)i * DDF, eb2 + (size_t)i * D_, f,
                 BS_, D_, DFF_, 1);
        add_ln_kernel<<<BS_, 128>>>(a, f, x);                        // x = LN(a+f)
    }
    // x now holds enc

    // ---------------- Decoder: only the last layer affects the output ------
    embed_kernel<<<BS_, 128>>>(tgt, emb, y0);
    {
        const int i = L_ - 1;
        run_gemm(y0, dWq1 + (size_t)i * DD, nullptr, q, BS_, D_, D_, 0);
        run_gemm(y0, dWk1 + (size_t)i * DD, nullptr, k, BS_, D_, D_, 0);
        run_gemm(y0, dWv1 + (size_t)i * DD, nullptr, v, BS_, D_, D_, 0);
        attn_kernel<<<attnGrid, 128>>>(q, k, v, tgt, attn, 1);       // causal
        run_gemm(attn, dWo1 + (size_t)i * DD, nullptr, a, BS_, D_, D_, 0);
        add_ln_kernel<<<BS_, 128>>>(y0, a, o);                       // o = LN(y0+a1)

        run_gemm(o, dWq2 + (size_t)i * DD, nullptr, q, BS_, D_, D_, 0);
        run_gemm(x, dWk2 + (size_t)i * DD, nullptr, k, BS_, D_, D_, 0);  // enc K
        run_gemm(x, dWv2 + (size_t)i * DD, nullptr, v, BS_, D_, D_, 0);  // enc V
        attn_kernel<<<attnGrid, 128>>>(q, k, v, src, attn, 0);       // cross
        run_gemm(attn, dWo2 + (size_t)i * DD, nullptr, a, BS_, D_, D_, 0);
        add_ln_kernel<<<BS_, 128>>>(o, a, o);                        // o = LN(o+a2)

        run_gemm(o, dW1 + (size_t)i * DDF, db1 + (size_t)i * DFF_, hbuf,
                 BS_, DFF_, D_, 2);
        run_gemm(hbuf, dW2 + (size_t)i * DDF, db2 + (size_t)i * D_, f,
                 BS_, D_, DFF_, 1);
        add_ln_kernel<<<BS_, 128>>>(o, f, o);                        // y = LN(o+f)
    }

    // ---------------- Logits ----------------
    run_gemm(o, Wout, bout, (float*)d_out, BS_, V_, D_, 1);
}

// round 7
// speedup vs baseline: 1.9725x; 1.9725x over previous
#include <cuda_runtime.h>
#include <cuda_bf16.h>
#include <math.h>
#include <stdint.h>

#define D_    512
#define S_    512
#define B_    4
#define H_    8
#define L_    6
#define DFF_  2048
#define V_    32000
#define BS_   (B_ * S_)
#define NEGV  (-1e10f)

// tcgen05 is arch-specific ("a") — only emit in the sm_103a/sm_100a pass.
#if defined(__CUDA_ARCH_FEAT_SM103_ALL) || defined(__CUDA_ARCH_FEAT_SM100_ALL) || defined(__CUDA_ARCH_FEAT_SM101_ALL)
#define HAS_TC 1
#else
#define HAS_TC 0
#endif

typedef __nv_bfloat16  bf16;
typedef __nv_bfloat162 bf162;

// ---------------------------------------------------------------------------
// Scratch (device globals; no allocation allowed)
// ---------------------------------------------------------------------------
__device__ float g_x[BS_ * D_];
__device__ float g_q[BS_ * D_];
__device__ float g_k[BS_ * D_];
__device__ float g_v[BS_ * D_];
__device__ float g_a[BS_ * D_];
__device__ float g_out[BS_ * D_];
__device__ float g_f[BS_ * D_];
__device__ float g_y0[BS_ * D_];
__device__ float g_o[BS_ * D_];

// bf16 hi/lo shadows (GEMM A-operands)
__device__ bf16 g_xh[BS_ * D_],   g_xl[BS_ * D_];
__device__ bf16 g_outh[BS_ * D_], g_outl[BS_ * D_];
__device__ bf16 g_ath[BS_ * D_],  g_atl[BS_ * D_];
__device__ bf16 g_y0h[BS_ * D_],  g_y0l[BS_ * D_];
__device__ bf16 g_oh[BS_ * D_],   g_ol[BS_ * D_];
__device__ bf16 g_hh[BS_ * DFF_], g_hl[BS_ * DFF_];

// Transposed+split weights arena (element offsets)
#define O_EWQ   0ull
#define O_EWK   1572864ull
#define O_EWV   3145728ull
#define O_EWO   4718592ull
#define O_EW1   6291456ull
#define O_EW2   12582912ull
#define O_DWQ1  18874368ull
#define O_DWK1  19136512ull
#define O_DWV1  19398656ull
#define O_DWO1  19660800ull
#define O_DWQ2  19922944ull
#define O_DWK2  20185088ull
#define O_DWV2  20447232ull
#define O_DWO2  20709376ull
#define O_DW1   20971520ull
#define O_DW2   22020096ull
#define O_WOUT  23068672ull
#define NWTOT   39452672ull
__device__ bf16 g_wh[NWTOT];
__device__ bf16 g_wl[NWTOT];

// ---------------------------------------------------------------------------
// PTX helpers
// ---------------------------------------------------------------------------
__device__ __forceinline__ uint32_t s2u(const void* p) {
    uint32_t a;
    asm("{ .reg .u64 t; cvta.to.shared.u64 t, %1; cvt.u32.u64 %0, t; }"
        : "=r"(a) : "l"(p));
    return a;
}
__device__ __forceinline__ uint32_t swz(uint32_t o) { return o ^ ((o >> 3) & 0x70u); }

__device__ __forceinline__ void sts128(uint32_t a, uint4 v) {
    asm volatile("st.shared.v4.b32 [%0], {%1,%2,%3,%4};"
                 :: "r"(a), "r"(v.x), "r"(v.y), "r"(v.z), "r"(v.w) : "memory");
}
__device__ __forceinline__ void mbar_init(uint32_t a, uint32_t c) {
    asm volatile("mbarrier.init.shared.b64 [%0], %1;" :: "r"(a), "r"(c) : "memory");
}
// acquire wait (ptx_helpers MBARRIER_WAIT_PARITY pattern)
__device__ __forceinline__ void mbar_wait(uint32_t a, uint32_t ph) {
    uint32_t done;
    asm volatile(
        "{\n\t.reg .pred p;\n\t"
        "mbarrier.try_wait.parity.acquire.cta.shared::cta.b64 p, [%1], %2;\n\t"
        "selp.b32 %0,1,0,p;\n\t}"
        : "=r"(done) : "r"(a), "r"(ph) : "memory");
    if (!done) {
        asm volatile(
            "{\n\t.reg .pred P1;\n\t"
            "WAIT_LOOP_%=:\n\t"
            "mbarrier.try_wait.parity.acquire.cta.shared::cta.b64 P1, [%0], %1, 0x989680;\n\t"
            "@P1 bra.uni WAIT_DONE_%=;\n\t"
            "bra.uni WAIT_LOOP_%=;\n\t"
            "WAIT_DONE_%=:\n\t}"
            :: "r"(a), "r"(ph) : "memory");
    }
}
#define FENCE_ASYNC() asm volatile("fence.proxy.async.shared::cta;" ::: "memory")

#if HAS_TC
__device__ __forceinline__ uint64_t mkdesc(uint32_t addr) {
    const uint64_t base = (2ull << 61) | (1ull << 46) | (64ull << 32) | (1ull << 16);
    return base | ((uint64_t)(addr >> 4) & 0x3FFFull);
}
__device__ __forceinline__ void mma_f16_ss(uint32_t d, uint64_t ad, uint64_t bd,
                                           uint32_t idesc, uint32_t en) {
    asm volatile(
        "{\n\t.reg .pred p;\n\tsetp.ne.u32 p, %5, 0;\n\t"
        "tcgen05.mma.cta_group::1.kind::f16 [%0], %1, %2, %3, {%4,%4,%4,%4}, p;\n\t}"
        :: "r"(d), "l"(ad), "l"(bd), "r"(idesc), "r"(0u), "r"(en) : "memory");
}
#define TC_ALLOC(sa, n)  asm volatile("tcgen05.alloc.cta_group::1.sync.aligned.shared::cta.b32 [%0], %1;" :: "r"(sa), "r"(n) : "memory")
#define TC_DEALLOC(t, n) asm volatile("tcgen05.dealloc.cta_group::1.sync.aligned.b32 %0, %1;" :: "r"(t), "r"(n))
#define TC_COMMIT(mb)    asm volatile("tcgen05.commit.cta_group::1.mbarrier::arrive::one.shared::cluster.b64 [%0];" :: "r"(mb) : "memory")
#define TC_FENCE_AFTER() asm volatile("tcgen05.fence::after_thread_sync;" ::: "memory")
#define TC_WAIT_LD()     asm volatile("tcgen05.wait::ld.sync.aligned;" ::: "memory")

#define TCLD32(r, a) \
    asm volatile( \
        "tcgen05.ld.sync.aligned.32x32b.x32.b32 " \
        "{%0, %1, %2, %3, %4, %5, %6, %7, " \
        " %8, %9, %10, %11, %12, %13, %14, %15, " \
        " %16, %17, %18, %19, %20, %21, %22, %23, " \
        " %24, %25, %26, %27, %28, %29, %30, %31}, [%32];" \
        : "=r"((r)[0]),  "=r"((r)[1]),  "=r"((r)[2]),  "=r"((r)[3]), \
          "=r"((r)[4]),  "=r"((r)[5]),  "=r"((r)[6]),  "=r"((r)[7]), \
          "=r"((r)[8]),  "=r"((r)[9]),  "=r"((r)[10]), "=r"((r)[11]), \
          "=r"((r)[12]), "=r"((r)[13]), "=r"((r)[14]), "=r"((r)[15]), \
          "=r"((r)[16]), "=r"((r)[17]), "=r"((r)[18]), "=r"((r)[19]), \
          "=r"((r)[20]), "=r"((r)[21]), "=r"((r)[22]), "=r"((r)[23]), \
          "=r"((r)[24]), "=r"((r)[25]), "=r"((r)[26]), "=r"((r)[27]), \
          "=r"((r)[28]), "=r"((r)[29]), "=r"((r)[30]), "=r"((r)[31]) \
        : "r"(a))
#endif  // HAS_TC

__device__ __forceinline__ void split_store4(bf16* __restrict__ Hh,
                                             bf16* __restrict__ Hl,
                                             size_t idx, float4 v) {
    bf16 hx = __float2bfloat16_rn(v.x), hy = __float2bfloat16_rn(v.y);
    bf16 hz = __float2bfloat16_rn(v.z), hw = __float2bfloat16_rn(v.w);
    bf16 lx = __float2bfloat16_rn(v.x - __bfloat162float(hx));
    bf16 ly = __float2bfloat16_rn(v.y - __bfloat162float(hy));
    bf16 lz = __float2bfloat16_rn(v.z - __bfloat162float(hz));
    bf16 lw = __float2bfloat16_rn(v.w - __bfloat162float(hw));
    bf162 p;
    p.x = hx; p.y = hy; *(bf162*)(Hh + idx)     = p;
    p.x = hz; p.y = hw; *(bf162*)(Hh + idx + 2) = p;
    p.x = lx; p.y = ly; *(bf162*)(Hl + idx)     = p;
    p.x = lz; p.y = lw; *(bf162*)(Hl + idx + 2) = p;
}

// ---------------------------------------------------------------------------
// Weight transpose + bf16 split: W [bz][K][N] fp32 -> out [bz][N][K] bf16 hi/lo
// ---------------------------------------------------------------------------
__global__ __launch_bounds__(256) void wconv_kernel(
    const float* __restrict__ W, bf16* __restrict__ oh, bf16* __restrict__ ol,
    int K, int N)
{
    __shared__ float tile[32][33];
    const int tx = threadIdx.x, ty = threadIdx.y;
    const int n0 = blockIdx.x * 32, k0 = blockIdx.y * 32, bz = blockIdx.z;
    const float* Wb = W + (size_t)bz * K * N;
    bf16* ohb = oh + (size_t)bz * K * N;
    bf16* olb = ol + (size_t)bz * K * N;
    #pragma unroll
    for (int i = 0; i < 4; i++)
        tile[ty + 8 * i][tx] = Wb[(size_t)(k0 + ty + 8 * i) * N + n0 + tx];
    __syncthreads();
    #pragma unroll
    for (int i = 0; i < 4; i++) {
        float v = tile[tx][ty + 8 * i];
        int n = n0 + ty + 8 * i, k = k0 + tx;
        size_t idx = (size_t)n * K + k;
        bf16 h = __float2bfloat16_rn(v);
        ohb[idx] = h;
        olb[idx] = __float2bfloat16_rn(v - __bfloat162float(h));
    }
}

// ---------------------------------------------------------------------------
// Embedding + positional encoding (+ bf16 split outputs)
// ---------------------------------------------------------------------------
__global__ __launch_bounds__(128) void embed_kernel(
    const int* __restrict__ ids, const float* __restrict__ emb,
    float* __restrict__ out, bf16* __restrict__ oh, bf16* __restrict__ ol)
{
    const int row = blockIdx.x;
    const int s   = row & (S_ - 1);
    const int tok = ids[row];
    const int t   = threadIdx.x;
    const float c = -logf(10000.0f) / (float)D_;
    float4 v;
    float tmp[4];
    #pragma unroll
    for (int j = 0; j < 4; j++) {
        int d  = t * 4 + j;
        int tj = d >> 1;
        float div = expf((float)(2 * tj) * c);
        float ang = (float)s * div;
        float pe  = (d & 1) ? cosf(ang) : sinf(ang);
        tmp[j] = emb[(size_t)tok * D_ + d] + pe;
    }
    v.x = tmp[0]; v.y = tmp[1]; v.z = tmp[2]; v.w = tmp[3];
    size_t base = (size_t)row * D_ + t * 4;
    *(float4*)(out + base) = v;
    split_store4(oh, ol, base, v);
}

// ---------------------------------------------------------------------------
// Fused residual + LayerNorm (+ bf16 split outputs)
// ---------------------------------------------------------------------------
__global__ __launch_bounds__(128) void add_ln_kernel(
    const float* __restrict__ A, const float* __restrict__ Bv,
    float* __restrict__ Out, bf16* __restrict__ Oh, bf16* __restrict__ Ol)
{
    const int row = blockIdx.x;
    const int t   = threadIdx.x;
    const size_t base = (size_t)row * D_ + t * 4;
    float4 a = *(const float4*)(A + base);
    float4 b = *(const float4*)(Bv + base);
    float4 vv;
    vv.x = a.x + b.x; vv.y = a.y + b.y; vv.z = a.z + b.z; vv.w = a.w + b.w;

    float s  = vv.x + vv.y + vv.z + vv.w;
    float sq = vv.x * vv.x + vv.y * vv.y + vv.z * vv.z + vv.w * vv.w;
    __shared__ float redS[4], redQ[4];
    #pragma unroll
    for (int off = 16; off > 0; off >>= 1) {
        s  += __shfl_xor_sync(0xffffffffu, s,  off);
        sq += __shfl_xor_sync(0xffffffffu, sq, off);
    }
    const int wid = t >> 5, lane = t & 31;
    if (lane == 0) { redS[wid] = s; redQ[wid] = sq; }
    __syncthreads();
    s  = redS[0] + redS[1] + redS[2] + redS[3];
    sq = redQ[0] + redQ[1] + redQ[2] + redQ[3];
    float mean = s * (1.0f / D_);
    float var  = sq * (1.0f / D_) - mean * mean;
    float inv  = rsqrtf(var + 1e-5f);
    float4 o;
    o.x = (vv.x - mean) * inv; o.y = (vv.y - mean) * inv;
    o.z = (vv.z - mean) * inv; o.w = (vv.w - mean) * inv;
    *(float4*)(Out + base) = o;
    split_store4(Oh, Ol, base, o);
}

// ---------------------------------------------------------------------------
// tcgen05 split-fp32 GEMM: C[M,N] = A[M,K] @ W[K,N]
// A as bf16 hi/lo [M,K]; W transposed bf16 hi/lo [N,K]. Tile 128x128, K-chunk
// 64, 2-stage pipeline, fp32 accum in TMEM.
// EPI: 0 none->C ; 1 +bias->C ; 3 +bias+relu-> bf16 hi/lo (Ch,Cl)
// ---------------------------------------------------------------------------
#define NT        128
#define GIDESC    ((1u<<4)|(1u<<7)|(1u<<10)|((NT/8)<<17)|(8u<<24))
#define STAGE_B   65536
#define SMEM_GEMM (2 * STAGE_B + 1024)   // +1024 alignment slack

template<int EPI>
__global__ __launch_bounds__(256)
void bgemm(const bf16* __restrict__ Ah, const bf16* __restrict__ Al,
           const bf16* __restrict__ Bh, const bf16* __restrict__ Bl,
           const float* __restrict__ bias, float* __restrict__ C,
           bf16* __restrict__ Ch, bf16* __restrict__ Cl,
           int M, int N, int K)
{
#if HAS_TC
    __shared__ __align__(16) uint32_t s_tptr[4];
    __shared__ __align__(16) uint64_t s_mbar[2];
    extern __shared__ char smem[];
    const uint32_t tiles = (s2u(smem) + 1023u) & ~1023u;   // slack covers align
    const uint32_t tptr  = s2u(s_tptr);
    const uint32_t mb[2] = { s2u(&s_mbar[0]), s2u(&s_mbar[1]) };

    const int t   = threadIdx.x;
    const int wid = t >> 5;
    const int bm  = blockIdx.y * 128, bn = blockIdx.x * NT;

    if (wid == 0) TC_ALLOC(tptr, 128);
    if (t == 0) { mbar_init(mb[0], 1); mbar_init(mb[1], 1); }
    __syncthreads();
    const uint32_t tmem = s_tptr[0];

    const int r  = t >> 3;     // 0..31
    const int ck = t & 7;      // 16B chunk within 128B row
    const int nch = K >> 6;
    int use[2] = {0, 0};

    for (int c = 0; c < nch; c++) {
        const int s = c & 1;
        if (use[s] > 0) mbar_wait(mb[s], (use[s] - 1) & 1);
        const uint32_t base = tiles + s * STAGE_B;
        const uint32_t aH = base, aL = base + 16384;
        const uint32_t bH = base + 32768, bL = base + 49152;
        const int k0 = c << 6;
        #pragma unroll
        for (int it = 0; it < 4; it++) {
            int row = r + it * 32;
            size_t g = (size_t)(bm + row) * K + k0 + ck * 8;
            uint32_t so = swz((uint32_t)(row * 128 + ck * 16));
            sts128(aH + so, *(const uint4*)(Ah + g));
            sts128(aL + so, *(const uint4*)(Al + g));
        }
        #pragma unroll
        for (int it = 0; it < 4; it++) {
            int row = r + it * 32;
            size_t g = (size_t)(bn + row) * K + k0 + ck * 8;
            uint32_t so = swz((uint32_t)(row * 128 + ck * 16));
            sts128(bH + so, *(const uint4*)(Bh + g));
            sts128(bL + so, *(const uint4*)(Bl + g));
        }
        FENCE_ASYNC();
        __syncthreads();
        if (t == 0) {
            uint64_t dah = mkdesc(aH), dal = mkdesc(aL);
            uint64_t dbh = mkdesc(bH), dbl = mkdesc(bL);
            #pragma unroll
            for (int j = 0; j < 4; j++)
                mma_f16_ss(tmem, dah + 2 * j, dbh + 2 * j, GIDESC,
                           (c == 0 && j == 0) ? 0u : 1u);
            #pragma unroll
            for (int j = 0; j < 4; j++)
                mma_f16_ss(tmem, dah + 2 * j, dbl + 2 * j, GIDESC, 1u);
            #pragma unroll
            for (int j = 0; j < 4; j++)
                mma_f16_ss(tmem, dal + 2 * j, dbh + 2 * j, GIDESC, 1u);
            TC_COMMIT(mb[s]);
        }
        use[s]++;
    }
    mbar_wait(mb[0], (use[0] - 1) & 1);
    if (use[1] > 0) mbar_wait(mb[1], (use[1] - 1) & 1);
    TC_FENCE_AFTER();

    // Epilogue: warp w -> row block (w&3), column half (w>>2)
    {
        const int sub = wid & 3, half = wid >> 2, lane = t & 31;
        const int rowg = bm + sub * 32 + lane;
        #pragma unroll
        for (int cc = 0; cc < 2; cc++) {
            const int col0 = half * 64 + cc * 32;
            uint32_t regs[32];
            TCLD32(regs, tmem + col0);
            TC_WAIT_LD();
            if (EPI == 0) {
                #pragma unroll
                for (int j = 0; j < 32; j += 4) {
                    float4 v;
                    v.x = __uint_as_float(regs[j]);
                    v.y = __uint_as_float(regs[j + 1]);
                    v.z = __uint_as_float(regs[j + 2]);
                    v.w = __uint_as_float(regs[j + 3]);
                    *(float4*)(C + (size_t)rowg * N + bn + col0 + j) = v;
                }
            } else if (EPI == 1) {
                #pragma unroll
                for (int j = 0; j < 32; j += 4) {
                    float4 bv = *(const float4*)(bias + bn + col0 + j);
                    float4 v;
                    v.x = __uint_as_float(regs[j])     + bv.x;
                    v.y = __uint_as_float(regs[j + 1]) + bv.y;
                    v.z = __uint_as_float(regs[j + 2]) + bv.z;
                    v.w = __uint_as_float(regs[j + 3]) + bv.w;
                    *(float4*)(C + (size_t)rowg * N + bn + col0 + j) = v;
                }
            } else {
                #pragma unroll
                for (int j = 0; j < 32; j += 4) {
                    float4 bv = *(const float4*)(bias + bn + col0 + j);
                    float4 v;
                    v.x = fmaxf(__uint_as_float(regs[j])     + bv.x, 0.f);
                    v.y = fmaxf(__uint_as_float(regs[j + 1]) + bv.y, 0.f);
                    v.z = fmaxf(__uint_as_float(regs[j + 2]) + bv.z, 0.f);
                    v.w = fmaxf(__uint_as_float(regs[j + 3]) + bv.w, 0.f);
                    split_store4(Ch, Cl, (size_t)rowg * N + bn + col0 + j, v);
                }
            }
        }
    }
    __syncthreads();
    if (wid == 0) TC_DEALLOC(tmem, 128);
#else
    // --- FFMA fallback (compute_103 generic pass only; never runs on GB300) ---
    const int t  = threadIdx.x;
    const int bm = blockIdx.y * 128, bn = blockIdx.x * NT;
    const int r0 = (t >> 4) * 8;
    const int c0 = (t & 15) * 8;
    float acc[8][8];
    #pragma unroll
    for (int i = 0; i < 8; i++)
        #pragma unroll
        for (int j = 0; j < 8; j++) acc[i][j] = 0.f;
    for (int k = 0; k < K; k++) {
        float av[8], bv[8];
        #pragma unroll
        for (int i = 0; i < 8; i++) {
            size_t ga = (size_t)(bm + r0 + i) * K + k;
            av[i] = __bfloat162float(Ah[ga]) + __bfloat162float(Al[ga]);
            size_t gb = (size_t)(bn + c0 + i) * K + k;
            bv[i] = __bfloat162float(Bh[gb]) + __bfloat162float(Bl[gb]);
        }
        #pragma unroll
        for (int i = 0; i < 8; i++)
            #pragma unroll
            for (int j = 0; j < 8; j++)
                acc[i][j] += av[i] * bv[j];
    }
    #pragma unroll
    for (int i = 0; i < 8; i++) {
        #pragma unroll
        for (int j = 0; j < 8; j++) {
            float v = acc[i][j];
            if (EPI >= 1) v += bias[bn + c0 + j];
            if (EPI == 3) v = fmaxf(v, 0.f);
            size_t idx = (size_t)(bm + r0 + i) * N + bn + c0 + j;
            if (EPI == 3) {
                bf16 h = __float2bfloat16_rn(v);
                Ch[idx] = h;
                Cl[idx] = __float2bfloat16_rn(v - __bfloat162float(h));
            } else {
                C[idx] = v;
            }
        }
    }
#endif
}

// ---------------------------------------------------------------------------
// Fused flash attention (epilogue writes bf16 hi/lo)
// ---------------------------------------------------------------------------
__global__ __launch_bounds__(128) void attn_kernel(
    const float* __restrict__ Q, const float* __restrict__ Km,
    const float* __restrict__ Vm, const int* __restrict__ kv_tok,
    bf16* __restrict__ Oh, bf16* __restrict__ Ol, int causal)
{
    __shared__ float4 Qs[16][16];
    __shared__ float4 Buf[128 * 17];
    __shared__ float  Ssc[16][128];
    __shared__ float  mstat[16], lstat[16], corrS[16];

    const int t  = threadIdx.x;
    const int qt = blockIdx.x, h = blockIdx.y, b = blockIdx.z;
    const int q0g = qt * 16;
    const size_t hcol = (size_t)h * 64;
    {
        const size_t baseQ = ((size_t)(b * S_ + q0g)) * D_ + hcol;
        #pragma unroll
        for (int it = 0; it < 2; it++) {
            int idx = t + it * 128;
            int r = idx >> 4, c4 = idx & 15;
            Qs[r][c4] = *(const float4*)(Q + baseQ + (size_t)r * D_ + c4 * 4);
        }
    }
    if (t < 16) { mstat[t] = -1e30f; lstat[t] = 0.f; }

    float4 oa0 = make_float4(0.f, 0.f, 0.f, 0.f);
    float4 oa1 = make_float4(0.f, 0.f, 0.f, 0.f);
    const int qiA = (t >> 4) * 2;
    const int dA  = (t & 15);
    const int qiS = (t >> 5);
    const int kjS = (t & 31);

    for (int kb = 0; kb < 4; kb++) {
        __syncthreads();
        {
            const size_t baseK = ((size_t)(b * S_ + kb * 128)) * D_ + hcol;
            #pragma unroll
            for (int it = 0; it < 16; it++) {
                int idx = t + it * 128;
                int r = idx >> 4, c4 = idx & 15;
                Buf[r * 17 + c4] =
                    *(const float4*)(Km + baseK + (size_t)r * D_ + c4 * 4);
            }
        }
        __syncthreads();
        {
            float acc[4][4];
            #pragma unroll
            for (int qq = 0; qq < 4; qq++)
                #pragma unroll
                for (int kk = 0; kk < 4; kk++) acc[qq][kk] = 0.f;
            #pragma unroll
            for (int d4 = 0; d4 < 16; d4++) {
                float4 kv[4];
                #pragma unroll
                for (int kk = 0; kk < 4; kk++)
                    kv[kk] = Buf[(kjS + 32 * kk) * 17 + d4];
                #pragma unroll
                for (int qq = 0; qq < 4; qq++) {
                    float4 qv = Qs[qiS + 4 * qq][d4];
                    #pragma unroll
                    for (int kk = 0; kk < 4; kk++) {
                        acc[qq][kk] += qv.x * kv[kk].x + qv.y * kv[kk].y
                                     + qv.z * kv[kk].z + qv.w * kv[kk].w;
                    }
                }
            }
            #pragma unroll
            for (int qq = 0; qq < 4; qq++) {
                int qi = qiS + 4 * qq;
                int qg = q0g + qi;
                #pragma unroll
                for (int kk = 0; kk < 4; kk++) {
                    int kj = kjS + 32 * kk;
                    int kg = kb * 128 + kj;
                    float s = acc[qq][kk] * 0.125f;
                    if (kv_tok[b * S_ + kg] == 0) s += NEGV;
                    if (causal && kg > qg) s += NEGV;
                    Ssc[qi][kj] = s;
                }
            }
        }
        __syncthreads();
        {
            int row = t >> 3, l8 = t & 7;
            float mloc = -1e30f;
            #pragma unroll
            for (int c = 0; c < 16; c++)
                mloc = fmaxf(mloc, Ssc[row][l8 + 8 * c]);
            #pragma unroll
            for (int off = 4; off > 0; off >>= 1)
                mloc = fmaxf(mloc, __shfl_xor_sync(0xffffffffu, mloc, off));
            float m_old = mstat[row];
            float m_new = fmaxf(m_old, mloc);
            float ssum = 0.f;
            #pragma unroll
            for (int c = 0; c < 16; c++) {
                float p = expf(Ssc[row][l8 + 8 * c] - m_new);
                Ssc[row][l8 + 8 * c] = p;
                ssum += p;
            }
            #pragma unroll
            for (int off = 4; off > 0; off >>= 1)
                ssum += __shfl_xor_sync(0xffffffffu, ssum, off);
            if (l8 == 0) {
                float corr = expf(m_old - m_new);
                corrS[row] = corr;
                lstat[row] = lstat[row] * corr + ssum;
                mstat[row] = m_new;
            }
        }
        __syncthreads();
        {
            const size_t baseV = ((size_t)(b * S_ + kb * 128)) * D_ + hcol;
            #pragma unroll
            for (int it = 0; it < 16; it++) {
                int idx = t + it * 128;
                int r = idx >> 4, c4 = idx & 15;
                Buf[r * 17 + c4] =
                    *(const float4*)(Vm + baseV + (size_t)r * D_ + c4 * 4);
            }
        }
        __syncthreads();
        {
            float c0 = corrS[qiA], c1 = corrS[qiA + 1];
            oa0.x *= c0; oa0.y *= c0; oa0.z *= c0; oa0.w *= c0;
            oa1.x *= c1; oa1.y *= c1; oa1.z *= c1; oa1.w *= c1;
            #pragma unroll 4
            for (int kj = 0; kj < 128; kj++) {
                float p0 = Ssc[qiA][kj];
                float p1 = Ssc[qiA + 1][kj];
                float4 vv = Buf[kj * 17 + dA];
                oa0.x += p0 * vv.x; oa0.y += p0 * vv.y;
                oa0.z += p0 * vv.z; oa0.w += p0 * vv.w;
                oa1.x += p1 * vv.x; oa1.y += p1 * vv.y;
                oa1.z += p1 * vv.z; oa1.w += p1 * vv.w;
            }
        }
    }
    __syncthreads();
    {
        float inv0 = 1.f / lstat[qiA];
        float inv1 = 1.f / lstat[qiA + 1];
        float4 r0 = make_float4(oa0.x * inv0, oa0.y * inv0, oa0.z * inv0, oa0.w * inv0);
        float4 r1 = make_float4(oa1.x * inv1, oa1.y * inv1, oa1.z * inv1, oa1.w * inv1);
        size_t base0 = ((size_t)(b * S_ + q0g + qiA)) * D_ + hcol + dA * 4;
        size_t base1 = ((size_t)(b * S_ + q0g + qiA + 1)) * D_ + hcol + dA * 4;
        split_store4(Oh, Ol, base0, r0);
        split_store4(Oh, Ol, base1, r1);
    }
}

// ---------------------------------------------------------------------------
// Host driver
// ---------------------------------------------------------------------------
static inline void run_bgemm(int epi, const bf16* Ah, const bf16* Al,
                             const bf16* Bh, const bf16* Bl, const float* bias,
                             float* C, bf16* Ch, bf16* Cl, int M, int N, int K)
{
    dim3 grid(N / NT, M / 128);
    if (epi == 0)
        bgemm<0><<<grid, 256, SMEM_GEMM>>>(Ah, Al, Bh, Bl, bias, C, Ch, Cl, M, N, K);
    else if (epi == 1)
        bgemm<1><<<grid, 256, SMEM_GEMM>>>(Ah, Al, Bh, Bl, bias, C, Ch, Cl, M, N, K);
    else
        bgemm<3><<<grid, 256, SMEM_GEMM>>>(Ah, Al, Bh, Bl, bias, C, Ch, Cl, M, N, K);
}

extern "C" void kernel_launch(void* const* d_in, const int* in_sizes, int n_in,
                              void* d_out, int out_size)
{
    const int DD  = D_ * D_;
    const int DDF = D_ * DFF_;

    int iEWq, iEWk, iEWv, iEWo, iEW1, iEb1, iEW2, iEb2;
    int iDWq1, iDWk1, iDWv1, iDWo1, iDWq2, iDWk2, iDWv2, iDWo2;
    int iDW1, iDb1, iDW2, iDb2, iWout, iBout;
    if (n_in >= 8 && in_sizes[7] == L_ * DD) {
        iEWq = 3; iEWk = 4; iEWv = 5; iEWo = 6;
        iDWq1 = 7; iDWk1 = 8; iDWv1 = 9; iDWo1 = 10;
        iDWq2 = 11; iDWk2 = 12; iDWv2 = 13; iDWo2 = 14;
        iEW1 = 15; iEb1 = 16; iEW2 = 17; iEb2 = 18;
        iDW1 = 19; iDb1 = 20; iDW2 = 21; iDb2 = 22;
        iWout = 23; iBout = 24;
    } else {
        iEWq = 3; iEWk = 4; iEWv = 5; iEWo = 6;
        iEW1 = 7; iEb1 = 8; iEW2 = 9; iEb2 = 10;
        iDWq1 = 11; iDWk1 = 12; iDWv1 = 13; iDWo1 = 14;
        iDWq2 = 15; iDWk2 = 16; iDWv2 = 17; iDWo2 = 18;
        iDW1 = 19; iDb1 = 20; iDW2 = 21; iDb2 = 22;
        iWout = 23; iBout = 24;
    }

    const int*   src  = (const int*)d_in[0];
    const int*   tgt  = (const int*)d_in[1];
    const float* emb  = (const float*)d_in[2];
    const float* eWq  = (const float*)d_in[iEWq];
    const float* eWk  = (const float*)d_in[iEWk];
    const float* eWv  = (const float*)d_in[iEWv];
    const float* eWo  = (const float*)d_in[iEWo];
    const float* eW1  = (const float*)d_in[iEW1];
    const float* eb1  = (const float*)d_in[iEb1];
    const float* eW2  = (const float*)d_in[iEW2];
    const float* eb2  = (const float*)d_in[iEb2];
    const float* dWq1 = (const float*)d_in[iDWq1];
    const float* dWk1 = (const float*)d_in[iDWk1];
    const float* dWv1 = (const float*)d_in[iDWv1];
    const float* dWo1 = (const float*)d_in[iDWo1];
    const float* dWq2 = (const float*)d_in[iDWq2];
    const float* dWk2 = (const float*)d_in[iDWk2];
    const float* dWv2 = (const float*)d_in[iDWv2];
    const float* dWo2 = (const float*)d_in[iDWo2];
    const float* dW1  = (const float*)d_in[iDW1];
    const float* db1  = (const float*)d_in[iDb1];
    const float* dW2  = (const float*)d_in[iDW2];
    const float* db2  = (const float*)d_in[iDb2];
    const float* Wout = (const float*)d_in[iWout];
    const float* bout = (const float*)d_in[iBout];

    cudaFuncSetAttribute(bgemm<0>, cudaFuncAttributeMaxDynamicSharedMemorySize, SMEM_GEMM);
    cudaFuncSetAttribute(bgemm<1>, cudaFuncAttributeMaxDynamicSharedMemorySize, SMEM_GEMM);
    cudaFuncSetAttribute(bgemm<3>, cudaFuncAttributeMaxDynamicSharedMemorySize, SMEM_GEMM);

    float *x, *q, *k, *v, *a, *out, *f, *y0, *o;
    cudaGetSymbolAddress((void**)&x,   g_x);
    cudaGetSymbolAddress((void**)&q,   g_q);
    cudaGetSymbolAddress((void**)&k,   g_k);
    cudaGetSymbolAddress((void**)&v,   g_v);
    cudaGetSymbolAddress((void**)&a,   g_a);
    cudaGetSymbolAddress((void**)&out, g_out);
    cudaGetSymbolAddress((void**)&f,   g_f);
    cudaGetSymbolAddress((void**)&y0,  g_y0);
    cudaGetSymbolAddress((void**)&o,   g_o);

    bf16 *xh, *xl, *outh, *outl, *ath, *atl, *y0h, *y0l, *oh, *ol, *hh, *hl, *wh, *wl;
    cudaGetSymbolAddress((void**)&xh,   g_xh);
    cudaGetSymbolAddress((void**)&xl,   g_xl);
    cudaGetSymbolAddress((void**)&outh, g_outh);
    cudaGetSymbolAddress((void**)&outl, g_outl);
    cudaGetSymbolAddress((void**)&ath,  g_ath);
    cudaGetSymbolAddress((void**)&atl,  g_atl);
    cudaGetSymbolAddress((void**)&y0h,  g_y0h);
    cudaGetSymbolAddress((void**)&y0l,  g_y0l);
    cudaGetSymbolAddress((void**)&oh,   g_oh);
    cudaGetSymbolAddress((void**)&ol,   g_ol);
    cudaGetSymbolAddress((void**)&hh,   g_hh);
    cudaGetSymbolAddress((void**)&hl,   g_hl);
    cudaGetSymbolAddress((void**)&wh,   g_wh);
    cudaGetSymbolAddress((void**)&wl,   g_wl);

    // ---- Weight conversion (transpose + bf16 split) ----
    dim3 blk(32, 8);
    wconv_kernel<<<dim3(16, 16, 6), blk>>>(eWq, wh + O_EWQ, wl + O_EWQ, D_, D_);
    wconv_kernel<<<dim3(16, 16, 6), blk>>>(eWk, wh + O_EWK, wl + O_EWK, D_, D_);
    wconv_kernel<<<dim3(16, 16, 6), blk>>>(eWv, wh + O_EWV, wl + O_EWV, D_, D_);
    wconv_kernel<<<dim3(16, 16, 6), blk>>>(eWo, wh + O_EWO, wl + O_EWO, D_, D_);
    wconv_kernel<<<dim3(64, 16, 6), blk>>>(eW1, wh + O_EW1, wl + O_EW1, D_, DFF_);
    wconv_kernel<<<dim3(16, 64, 6), blk>>>(eW2, wh + O_EW2, wl + O_EW2, DFF_, D_);
    const int li = L_ - 1;
    wconv_kernel<<<dim3(16, 16, 1), blk>>>(dWq1 + (size_t)li * DD, wh + O_DWQ1, wl + O_DWQ1, D_, D_);
    wconv_kernel<<<dim3(16, 16, 1), blk>>>(dWk1 + (size_t)li * DD, wh + O_DWK1, wl + O_DWK1, D_, D_);
    wconv_kernel<<<dim3(16, 16, 1), blk>>>(dWv1 + (size_t)li * DD, wh + O_DWV1, wl + O_DWV1, D_, D_);
    wconv_kernel<<<dim3(16, 16, 1), blk>>>(dWo1 + (size_t)li * DD, wh + O_DWO1, wl + O_DWO1, D_, D_);
    wconv_kernel<<<dim3(16, 16, 1), blk>>>(dWq2 + (size_t)li * DD, wh + O_DWQ2, wl + O_DWQ2, D_, D_);
    wconv_kernel<<<dim3(16, 16, 1), blk>>>(dWk2 + (size_t)li * DD, wh + O_DWK2, wl + O_DWK2, D_, D_);
    wconv_kernel<<<dim3(16, 16, 1), blk>>>(dWv2 + (size_t)li * DD, wh + O_DWV2, wl + O_DWV2, D_, D_);
    wconv_kernel<<<dim3(16, 16, 1), blk>>>(dWo2 + (size_t)li * DD, wh + O_DWO2, wl + O_DWO2, D_, D_);
    wconv_kernel<<<dim3(64, 16, 1), blk>>>(dW1 + (size_t)li * DDF, wh + O_DW1, wl + O_DW1, D_, DFF_);
    wconv_kernel<<<dim3(16, 64, 1), blk>>>(dW2 + (size_t)li * DDF, wh + O_DW2, wl + O_DW2, DFF_, D_);
    wconv_kernel<<<dim3(1000, 16, 1), blk>>>(Wout, wh + O_WOUT, wl + O_WOUT, D_, V_);

    const dim3 attnGrid(S_ / 16, H_, B_);

    // ---------------- Encoder ----------------
    embed_kernel<<<BS_, 128>>>(src, emb, x, xh, xl);
    for (int i = 0; i < L_; i++) {
        run_bgemm(0, xh, xl, wh + O_EWQ + (size_t)i * DD, wl + O_EWQ + (size_t)i * DD,
                  nullptr, q, nullptr, nullptr, BS_, D_, D_);
        run_bgemm(0, xh, xl, wh + O_EWK + (size_t)i * DD, wl + O_EWK + (size_t)i * DD,
                  nullptr, k, nullptr, nullptr, BS_, D_, D_);
        run_bgemm(0, xh, xl, wh + O_EWV + (size_t)i * DD, wl + O_EWV + (size_t)i * DD,
                  nullptr, v, nullptr, nullptr, BS_, D_, D_);
        attn_kernel<<<attnGrid, 128>>>(q, k, v, src, ath, atl, 0);
        run_bgemm(0, ath, atl, wh + O_EWO + (size_t)i * DD, wl + O_EWO + (size_t)i * DD,
                  nullptr, a, nullptr, nullptr, BS_, D_, D_);
        add_ln_kernel<<<BS_, 128>>>(x, a, out, outh, outl);
        run_bgemm(3, outh, outl, wh + O_EW1 + (size_t)i * DDF, wl + O_EW1 + (size_t)i * DDF,
                  eb1 + (size_t)i * DFF_, nullptr, hh, hl, BS_, DFF_, D_);
        run_bgemm(1, hh, hl, wh + O_EW2 + (size_t)i * DDF, wl + O_EW2 + (size_t)i * DDF,
                  eb2 + (size_t)i * D_, f, nullptr, nullptr, BS_, D_, DFF_);
        add_ln_kernel<<<BS_, 128>>>(a, f, x, xh, xl);
    }

    // ---------------- Decoder: only the last layer matters ----------------
    embed_kernel<<<BS_, 128>>>(tgt, emb, y0, y0h, y0l);
    {
        run_bgemm(0, y0h, y0l, wh + O_DWQ1, wl + O_DWQ1, nullptr, q, nullptr, nullptr, BS_, D_, D_);
        run_bgemm(0, y0h, y0l, wh + O_DWK1, wl + O_DWK1, nullptr, k, nullptr, nullptr, BS_, D_, D_);
        run_bgemm(0, y0h, y0l, wh + O_DWV1, wl + O_DWV1, nullptr, v, nullptr, nullptr, BS_, D_, D_);
        attn_kernel<<<attnGrid, 128>>>(q, k, v, tgt, ath, atl, 1);
        run_bgemm(0, ath, atl, wh + O_DWO1, wl + O_DWO1, nullptr, a, nullptr, nullptr, BS_, D_, D_);
        add_ln_kernel<<<BS_, 128>>>(y0, a, o, oh, ol);

        run_bgemm(0, oh, ol, wh + O_DWQ2, wl + O_DWQ2, nullptr, q, nullptr, nullptr, BS_, D_, D_);
        run_bgemm(0, xh, xl, wh + O_DWK2, wl + O_DWK2, nullptr, k, nullptr, nullptr, BS_, D_, D_);
        run_bgemm(0, xh, xl, wh + O_DWV2, wl + O_DWV2, nullptr, v, nullptr, nullptr, BS_, D_, D_);
        attn_kernel<<<attnGrid, 128>>>(q, k, v, src, ath, atl, 0);
        run_bgemm(0, ath, atl, wh + O_DWO2, wl + O_DWO2, nullptr, a, nullptr, nullptr, BS_, D_, D_);
        add_ln_kernel<<<BS_, 128>>>(o, a, o, oh, ol);

        run_bgemm(3, oh, ol, wh + O_DW1, wl + O_DW1, db1 + (size_t)li * DFF_,
                  nullptr, hh, hl, BS_, DFF_, D_);
        run_bgemm(1, hh, hl, wh + O_DW2, wl + O_DW2, db2 + (size_t)li * D_,
                  f, nullptr, nullptr, BS_, D_, DFF_);
        add_ln_kernel<<<BS_, 128>>>(o, f, o, oh, ol);
    }

    // ---------------- Logits ----------------
    run_bgemm(1, oh, ol, wh + O_WOUT, wl + O_WOUT, bout, (float*)d_out,
              nullptr, nullptr, BS_, V_, D_);
}

// round 8
// speedup vs baseline: 2.8206x; 1.4299x over previous
#include <cuda_runtime.h>
#include <cuda_bf16.h>
#include <math.h>
#include <stdint.h>

#define D_    512
#define S_    512
#define B_    4
#define H_    8
#define L_    6
#define DFF_  2048
#define V_    32000
#define BS_   (B_ * S_)
#define NEGV  (-1e10f)

#if defined(__CUDA_ARCH_FEAT_SM103_ALL) || defined(__CUDA_ARCH_FEAT_SM100_ALL) || defined(__CUDA_ARCH_FEAT_SM101_ALL)
#define HAS_TC 1
#else
#define HAS_TC 0
#endif

typedef __nv_bfloat16  bf16;
typedef __nv_bfloat162 bf162;

// ---------------------------------------------------------------------------
// Scratch (device globals)
// ---------------------------------------------------------------------------
__device__ float g_x[BS_ * D_];
__device__ float g_q[BS_ * D_];
__device__ float g_a[BS_ * D_];
__device__ float g_out[BS_ * D_];
__device__ float g_f[BS_ * D_];
__device__ float g_y0[BS_ * D_];
__device__ float g_o[BS_ * D_];
__device__ float g_qkv[BS_ * 3 * D_];   // fused QKV output (pitch 1536)
__device__ float g_kv2[BS_ * 2 * D_];   // fused cross K,V (pitch 1024)

__device__ bf16 g_xh[BS_ * D_],   g_xl[BS_ * D_];
__device__ bf16 g_outh[BS_ * D_], g_outl[BS_ * D_];
__device__ bf16 g_ath[BS_ * D_],  g_atl[BS_ * D_];
__device__ bf16 g_y0h[BS_ * D_],  g_y0l[BS_ * D_];
__device__ bf16 g_oh[BS_ * D_],   g_ol[BS_ * D_];
__device__ bf16 g_hh[BS_ * DFF_], g_hl[BS_ * DFF_];

// Transposed+split weights arena (element offsets). Per-layer-contiguous QKV.
#define DD      (512ull * 512ull)
#define DDF     (512ull * 2048ull)
#define O_EQKV  0ull                       // 6 layers x [Wq;Wk;Wv]  (3DD each)
#define O_EWO   4718592ull                 // 6 x DD
#define O_EW1   6291456ull                 // 6 x DDF
#define O_EW2   12582912ull                // 6 x DDF
#define O_DQKV1 18874368ull                // [Wq1;Wk1;Wv1] 3DD
#define O_DWO1  19660800ull
#define O_DWQ2  19922944ull
#define O_DKV2  20185088ull                // [Wk2;Wv2] 2DD
#define O_DWO2  20709376ull
#define O_DW1   20971520ull
#define O_DW2   22020096ull
#define O_WOUT  23068672ull
#define NWTOT   39452672ull
__device__ bf16 g_wh[NWTOT];
__device__ bf16 g_wl[NWTOT];

// ---------------------------------------------------------------------------
// PTX helpers
// ---------------------------------------------------------------------------
__device__ __forceinline__ uint32_t s2u(const void* p) {
    uint32_t a;
    asm("{ .reg .u64 t; cvta.to.shared.u64 t, %1; cvt.u32.u64 %0, t; }"
        : "=r"(a) : "l"(p));
    return a;
}
__device__ __forceinline__ uint32_t swz(uint32_t o) { return o ^ ((o >> 3) & 0x70u); }

__device__ __forceinline__ void mbar_init(uint32_t a, uint32_t c) {
    asm volatile("mbarrier.init.shared.b64 [%0], %1;" :: "r"(a), "r"(c) : "memory");
}
__device__ __forceinline__ void mbar_wait(uint32_t a, uint32_t ph) {
    uint32_t done;
    asm volatile(
        "{\n\t.reg .pred p;\n\t"
        "mbarrier.try_wait.parity.acquire.cta.shared::cta.b64 p, [%1], %2;\n\t"
        "selp.b32 %0,1,0,p;\n\t}"
        : "=r"(done) : "r"(a), "r"(ph) : "memory");
    if (!done) {
        asm volatile(
            "{\n\t.reg .pred P1;\n\t"
            "WAIT_LOOP_%=:\n\t"
            "mbarrier.try_wait.parity.acquire.cta.shared::cta.b64 P1, [%0], %1, 0x989680;\n\t"
            "@P1 bra.uni WAIT_DONE_%=;\n\t"
            "bra.uni WAIT_LOOP_%=;\n\t"
            "WAIT_DONE_%=:\n\t}"
            :: "r"(a), "r"(ph) : "memory");
    }
}
#define FENCE_ASYNC() asm volatile("fence.proxy.async.shared::cta;" ::: "memory")

__device__ __forceinline__ void cpasync16(uint32_t saddr, const void* g) {
    asm volatile("cp.async.cg.shared.global [%0], [%1], 16;"
                 :: "r"(saddr), "l"(g));
}
#define CP_COMMIT() asm volatile("cp.async.commit_group;" ::: "memory")
#define CP_WAIT1()  asm volatile("cp.async.wait_group 1;" ::: "memory")
#define CP_WAIT0()  asm volatile("cp.async.wait_group 0;" ::: "memory")

#if HAS_TC
__device__ __forceinline__ uint64_t mkdesc(uint32_t addr) {
    const uint64_t base = (2ull << 61) | (1ull << 46) | (64ull << 32) | (1ull << 16);
    return base | ((uint64_t)(addr >> 4) & 0x3FFFull);
}
__device__ __forceinline__ void mma_f16_ss(uint32_t d, uint64_t ad, uint64_t bd,
                                           uint32_t idesc, uint32_t en) {
    asm volatile(
        "{\n\t.reg .pred p;\n\tsetp.ne.u32 p, %5, 0;\n\t"
        "tcgen05.mma.cta_group::1.kind::f16 [%0], %1, %2, %3, {%4,%4,%4,%4}, p;\n\t}"
        :: "r"(d), "l"(ad), "l"(bd), "r"(idesc), "r"(0u), "r"(en) : "memory");
}
#define TC_ALLOC(sa, n)  asm volatile("tcgen05.alloc.cta_group::1.sync.aligned.shared::cta.b32 [%0], %1;" :: "r"(sa), "r"(n) : "memory")
#define TC_DEALLOC(t, n) asm volatile("tcgen05.dealloc.cta_group::1.sync.aligned.b32 %0, %1;" :: "r"(t), "r"(n))
#define TC_COMMIT(mb)    asm volatile("tcgen05.commit.cta_group::1.mbarrier::arrive::one.shared::cluster.b64 [%0];" :: "r"(mb) : "memory")
#define TC_FENCE_AFTER() asm volatile("tcgen05.fence::after_thread_sync;" ::: "memory")
#define TC_WAIT_LD()     asm volatile("tcgen05.wait::ld.sync.aligned;" ::: "memory")

#define TCLD32(r, a) \
    asm volatile( \
        "tcgen05.ld.sync.aligned.32x32b.x32.b32 " \
        "{%0, %1, %2, %3, %4, %5, %6, %7, " \
        " %8, %9, %10, %11, %12, %13, %14, %15, " \
        " %16, %17, %18, %19, %20, %21, %22, %23, " \
        " %24, %25, %26, %27, %28, %29, %30, %31}, [%32];" \
        : "=r"((r)[0]),  "=r"((r)[1]),  "=r"((r)[2]),  "=r"((r)[3]), \
          "=r"((r)[4]),  "=r"((r)[5]),  "=r"((r)[6]),  "=r"((r)[7]), \
          "=r"((r)[8]),  "=r"((r)[9]),  "=r"((r)[10]), "=r"((r)[11]), \
          "=r"((r)[12]), "=r"((r)[13]), "=r"((r)[14]), "=r"((r)[15]), \
          "=r"((r)[16]), "=r"((r)[17]), "=r"((r)[18]), "=r"((r)[19]), \
          "=r"((r)[20]), "=r"((r)[21]), "=r"((r)[22]), "=r"((r)[23]), \
          "=r"((r)[24]), "=r"((r)[25]), "=r"((r)[26]), "=r"((r)[27]), \
          "=r"((r)[28]), "=r"((r)[29]), "=r"((r)[30]), "=r"((r)[31]) \
        : "r"(a))
#endif  // HAS_TC

__device__ __forceinline__ void split_store4(bf16* __restrict__ Hh,
                                             bf16* __restrict__ Hl,
                                             size_t idx, float4 v) {
    bf16 hx = __float2bfloat16_rn(v.x), hy = __float2bfloat16_rn(v.y);
    bf16 hz = __float2bfloat16_rn(v.z), hw = __float2bfloat16_rn(v.w);
    bf16 lx = __float2bfloat16_rn(v.x - __bfloat162float(hx));
    bf16 ly = __float2bfloat16_rn(v.y - __bfloat162float(hy));
    bf16 lz = __float2bfloat16_rn(v.z - __bfloat162float(hz));
    bf16 lw = __float2bfloat16_rn(v.w - __bfloat162float(hw));
    bf162 p;
    p.x = hx; p.y = hy; *(bf162*)(Hh + idx)     = p;
    p.x = hz; p.y = hw; *(bf162*)(Hh + idx + 2) = p;
    p.x = lx; p.y = ly; *(bf162*)(Hl + idx)     = p;
    p.x = lz; p.y = lw; *(bf162*)(Hl + idx + 2) = p;
}

// ---------------------------------------------------------------------------
// Weight transpose + bf16 split. Input layer z: W + z*K*N ([K][N] fp32).
// Output layer z: oh/ol + z*lstride, layout [N][K] bf16.
// ---------------------------------------------------------------------------
__global__ __launch_bounds__(256) void wconv_kernel(
    const float* __restrict__ W, bf16* __restrict__ oh, bf16* __restrict__ ol,
    int K, int N, uint64_t lstride)
{
    __shared__ float tile[32][33];
    const int tx = threadIdx.x, ty = threadIdx.y;
    const int n0 = blockIdx.x * 32, k0 = blockIdx.y * 32, bz = blockIdx.z;
    const float* Wb = W + (size_t)bz * K * N;
    bf16* ohb = oh + (size_t)bz * lstride;
    bf16* olb = ol + (size_t)bz * lstride;
    #pragma unroll
    for (int i = 0; i < 4; i++)
        tile[ty + 8 * i][tx] = Wb[(size_t)(k0 + ty + 8 * i) * N + n0 + tx];
    __syncthreads();
    #pragma unroll
    for (int i = 0; i < 4; i++) {
        float v = tile[tx][ty + 8 * i];
        int n = n0 + ty + 8 * i, k = k0 + tx;
        size_t idx = (size_t)n * K + k;
        bf16 h = __float2bfloat16_rn(v);
        ohb[idx] = h;
        olb[idx] = __float2bfloat16_rn(v - __bfloat162float(h));
    }
}

// ---------------------------------------------------------------------------
// Embedding + positional encoding (+ bf16 split)
// ---------------------------------------------------------------------------
__global__ __launch_bounds__(128) void embed_kernel(
    const int* __restrict__ ids, const float* __restrict__ emb,
    float* __restrict__ out, bf16* __restrict__ oh, bf16* __restrict__ ol)
{
    const int row = blockIdx.x;
    const int s   = row & (S_ - 1);
    const int tok = ids[row];
    const int t   = threadIdx.x;
    const float c = -logf(10000.0f) / (float)D_;
    float4 v;
    float tmp[4];
    #pragma unroll
    for (int j = 0; j < 4; j++) {
        int d  = t * 4 + j;
        int tj = d >> 1;
        float div = expf((float)(2 * tj) * c);
        float ang = (float)s * div;
        float pe  = (d & 1) ? cosf(ang) : sinf(ang);
        tmp[j] = emb[(size_t)tok * D_ + d] + pe;
    }
    v.x = tmp[0]; v.y = tmp[1]; v.z = tmp[2]; v.w = tmp[3];
    size_t base = (size_t)row * D_ + t * 4;
    *(float4*)(out + base) = v;
    split_store4(oh, ol, base, v);
}

// ---------------------------------------------------------------------------
// Fused residual + LayerNorm (+ bf16 split)
// ---------------------------------------------------------------------------
__global__ __launch_bounds__(128) void add_ln_kernel(
    const float* __restrict__ A, const float* __restrict__ Bv,
    float* __restrict__ Out, bf16* __restrict__ Oh, bf16* __restrict__ Ol)
{
    const int row = blockIdx.x;
    const int t   = threadIdx.x;
    const size_t base = (size_t)row * D_ + t * 4;
    float4 a = *(const float4*)(A + base);
    float4 b = *(const float4*)(Bv + base);
    float4 vv;
    vv.x = a.x + b.x; vv.y = a.y + b.y; vv.z = a.z + b.z; vv.w = a.w + b.w;

    float s  = vv.x + vv.y + vv.z + vv.w;
    float sq = vv.x * vv.x + vv.y * vv.y + vv.z * vv.z + vv.w * vv.w;
    __shared__ float redS[4], redQ[4];
    #pragma unroll
    for (int off = 16; off > 0; off >>= 1) {
        s  += __shfl_xor_sync(0xffffffffu, s,  off);
        sq += __shfl_xor_sync(0xffffffffu, sq, off);
    }
    const int wid = t >> 5, lane = t & 31;
    if (lane == 0) { redS[wid] = s; redQ[wid] = sq; }
    __syncthreads();
    s  = redS[0] + redS[1] + redS[2] + redS[3];
    sq = redQ[0] + redQ[1] + redQ[2] + redQ[3];
    float mean = s * (1.0f / D_);
    float var  = sq * (1.0f / D_) - mean * mean;
    float inv  = rsqrtf(var + 1e-5f);
    float4 o;
    o.x = (vv.x - mean) * inv; o.y = (vv.y - mean) * inv;
    o.z = (vv.z - mean) * inv; o.w = (vv.w - mean) * inv;
    *(float4*)(Out + base) = o;
    split_store4(Oh, Ol, base, o);
}

// ---------------------------------------------------------------------------
// tcgen05 split-fp32 GEMM, 3-stage cp.async pipeline.
// C[M,N] = A[M,K] @ W[K,N]; A bf16 hi/lo [M,K]; W transposed bf16 hi/lo [N,K].
// EPI: 0 none->C ; 1 +bias->C ; 3 +bias+relu-> bf16 hi/lo
// ---------------------------------------------------------------------------
#define NT        128
#define GIDESC    ((1u<<4)|(1u<<7)|(1u<<10)|((NT/8)<<17)|(8u<<24))
#define STAGE_B   65536
#define NSTG      3
#define SMEM_GEMM (NSTG * STAGE_B + 1024)

template<int EPI>
__global__ __launch_bounds__(256)
void bgemm(const bf16* __restrict__ Ah, const bf16* __restrict__ Al,
           const bf16* __restrict__ Bh, const bf16* __restrict__ Bl,
           const float* __restrict__ bias, float* __restrict__ C,
           bf16* __restrict__ Ch, bf16* __restrict__ Cl,
           int M, int N, int K)
{
#if HAS_TC
    __shared__ __align__(16) uint32_t s_tptr[4];
    __shared__ __align__(16) uint64_t s_mbar[NSTG];
    extern __shared__ char smem[];
    const uint32_t tiles = (s2u(smem) + 1023u) & ~1023u;
    const uint32_t tptr  = s2u(s_tptr);
    uint32_t mb[NSTG];
    #pragma unroll
    for (int i = 0; i < NSTG; i++) mb[i] = s2u(&s_mbar[i]);

    const int t   = threadIdx.x;
    const int wid = t >> 5;
    const int bm  = blockIdx.y * 128, bn = blockIdx.x * NT;

    if (wid == 0) TC_ALLOC(tptr, 128);
    if (t == 0) { 
        #pragma unroll
        for (int i = 0; i < NSTG; i++) mbar_init(mb[i], 1);
    }
    __syncthreads();
    const uint32_t tmem = s_tptr[0];

    const int r  = t >> 3;     // 0..31
    const int ck = t & 7;      // 16B chunk within 128B row
    const int nch = K >> 6;
    int use[NSTG];
    #pragma unroll
    for (int i = 0; i < NSTG; i++) use[i] = 0;

    // per-chunk load: 16 cp.async per thread into stage s
    auto load_chunk = [&](int c, int s) {
        const uint32_t base = tiles + s * STAGE_B;
        const uint32_t aH = base, aL = base + 16384;
        const uint32_t bH = base + 32768, bL = base + 49152;
        const int k0 = c << 6;
        #pragma unroll
        for (int it = 0; it < 4; it++) {
            int row = r + it * 32;
            size_t g = (size_t)(bm + row) * K + k0 + ck * 8;
            uint32_t so = swz((uint32_t)(row * 128 + ck * 16));
            cpasync16(aH + so, Ah + g);
            cpasync16(aL + so, Al + g);
        }
        #pragma unroll
        for (int it = 0; it < 4; it++) {
            int row = r + it * 32;
            size_t g = (size_t)(bn + row) * K + k0 + ck * 8;
            uint32_t so = swz((uint32_t)(row * 128 + ck * 16));
            cpasync16(bH + so, Bh + g);
            cpasync16(bL + so, Bl + g);
        }
        CP_COMMIT();
    };

    load_chunk(0, 0);
    for (int c = 0; c < nch; c++) {
        const int s = c % NSTG;
        if (c + 1 < nch) {
            const int s2 = (c + 1) % NSTG;
            if (use[s2] > 0) mbar_wait(mb[s2], (use[s2] - 1) & 1);
            load_chunk(c + 1, s2);
            CP_WAIT1();          // chunk c's group complete; c+1 in flight
        } else {
            CP_WAIT0();
        }
        FENCE_ASYNC();
        __syncthreads();
        if (t == 0) {
            const uint32_t base = tiles + s * STAGE_B;
            uint64_t dah = mkdesc(base),         dal = mkdesc(base + 16384);
            uint64_t dbh = mkdesc(base + 32768), dbl = mkdesc(base + 49152);
            #pragma unroll
            for (int j = 0; j < 4; j++)
                mma_f16_ss(tmem, dah + 2 * j, dbh + 2 * j, GIDESC,
                           (c == 0 && j == 0) ? 0u : 1u);
            #pragma unroll
            for (int j = 0; j < 4; j++)
                mma_f16_ss(tmem, dah + 2 * j, dbl + 2 * j, GIDESC, 1u);
            #pragma unroll
            for (int j = 0; j < 4; j++)
                mma_f16_ss(tmem, dal + 2 * j, dbh + 2 * j, GIDESC, 1u);
            TC_COMMIT(mb[s]);
        }
        use[s]++;
    }
    #pragma unroll
    for (int i = 0; i < NSTG; i++)
        if (use[i] > 0) mbar_wait(mb[i], (use[i] - 1) & 1);
    TC_FENCE_AFTER();

    // Epilogue: warp w -> row block (w&3), column half (w>>2)
    {
        const int sub = wid & 3, half = wid >> 2, lane = t & 31;
        const int rowg = bm + sub * 32 + lane;
        #pragma unroll
        for (int cc = 0; cc < 2; cc++) {
            const int col0 = half * 64 + cc * 32;
            uint32_t regs[32];
            TCLD32(regs, tmem + col0);
            TC_WAIT_LD();
            if (EPI == 0) {
                #pragma unroll
                for (int j = 0; j < 32; j += 4) {
                    float4 v;
                    v.x = __uint_as_float(regs[j]);
                    v.y = __uint_as_float(regs[j + 1]);
                    v.z = __uint_as_float(regs[j + 2]);
                    v.w = __uint_as_float(regs[j + 3]);
                    *(float4*)(C + (size_t)rowg * N + bn + col0 + j) = v;
                }
            } else if (EPI == 1) {
                #pragma unroll
                for (int j = 0; j < 32; j += 4) {
                    float4 bv = *(const float4*)(bias + bn + col0 + j);
                    float4 v;
                    v.x = __uint_as_float(regs[j])     + bv.x;
                    v.y = __uint_as_float(regs[j + 1]) + bv.y;
                    v.z = __uint_as_float(regs[j + 2]) + bv.z;
                    v.w = __uint_as_float(regs[j + 3]) + bv.w;
                    *(float4*)(C + (size_t)rowg * N + bn + col0 + j) = v;
                }
            } else {
                #pragma unroll
                for (int j = 0; j < 32; j += 4) {
                    float4 bv = *(const float4*)(bias + bn + col0 + j);
                    float4 v;
                    v.x = fmaxf(__uint_as_float(regs[j])     + bv.x, 0.f);
                    v.y = fmaxf(__uint_as_float(regs[j + 1]) + bv.y, 0.f);
                    v.z = fmaxf(__uint_as_float(regs[j + 2]) + bv.z, 0.f);
                    v.w = fmaxf(__uint_as_float(regs[j + 3]) + bv.w, 0.f);
                    split_store4(Ch, Cl, (size_t)rowg * N + bn + col0 + j, v);
                }
            }
        }
    }
    __syncthreads();
    if (wid == 0) TC_DEALLOC(tmem, 128);
#else
    // --- FFMA fallback (generic pass only; never runs on GB300) ---
    const int t  = threadIdx.x;
    const int bm = blockIdx.y * 128, bn = blockIdx.x * NT;
    const int r0 = (t >> 4) * 8;
    const int c0 = (t & 15) * 8;
    float acc[8][8];
    #pragma unroll
    for (int i = 0; i < 8; i++)
        #pragma unroll
        for (int j = 0; j < 8; j++) acc[i][j] = 0.f;
    for (int k = 0; k < K; k++) {
        float av[8], bv[8];
        #pragma unroll
        for (int i = 0; i < 8; i++) {
            size_t ga = (size_t)(bm + r0 + i) * K + k;
            av[i] = __bfloat162float(Ah[ga]) + __bfloat162float(Al[ga]);
            size_t gb = (size_t)(bn + c0 + i) * K + k;
            bv[i] = __bfloat162float(Bh[gb]) + __bfloat162float(Bl[gb]);
        }
        #pragma unroll
        for (int i = 0; i < 8; i++)
            #pragma unroll
            for (int j = 0; j < 8; j++)
                acc[i][j] += av[i] * bv[j];
    }
    #pragma unroll
    for (int i = 0; i < 8; i++) {
        #pragma unroll
        for (int j = 0; j < 8; j++) {
            float v = acc[i][j];
            if (EPI >= 1) v += bias[bn + c0 + j];
            if (EPI == 3) v = fmaxf(v, 0.f);
            size_t idx = (size_t)(bm + r0 + i) * N + bn + c0 + j;
            if (EPI == 3) {
                bf16 h = __float2bfloat16_rn(v);
                Ch[idx] = h;
                Cl[idx] = __float2bfloat16_rn(v - __bfloat162float(h));
            } else {
                C[idx] = v;
            }
        }
    }
#endif
}

// ---------------------------------------------------------------------------
// Fused flash attention; Q and K/V row pitches parameterized so the fused
// QKV / KV buffers are consumed in place. Output bf16 hi/lo, pitch D_.
// ---------------------------------------------------------------------------
__global__ __launch_bounds__(128) void attn_kernel(
    const float* __restrict__ Q, const float* __restrict__ Km,
    const float* __restrict__ Vm, int qpitch, int kpitch,
    const int* __restrict__ kv_tok,
    bf16* __restrict__ Oh, bf16* __restrict__ Ol, int causal)
{
    __shared__ float4 Qs[16][16];
    __shared__ float4 Buf[128 * 17];
    __shared__ float  Ssc[16][128];
    __shared__ float  mstat[16], lstat[16], corrS[16];

    const int t  = threadIdx.x;
    const int qt = blockIdx.x, h = blockIdx.y, b = blockIdx.z;
    const int q0g = qt * 16;
    const size_t hcol = (size_t)h * 64;
    {
        const size_t baseQ = ((size_t)(b * S_ + q0g)) * qpitch + hcol;
        #pragma unroll
        for (int it = 0; it < 2; it++) {
            int idx = t + it * 128;
            int r = idx >> 4, c4 = idx & 15;
            Qs[r][c4] = *(const float4*)(Q + baseQ + (size_t)r * qpitch + c4 * 4);
        }
    }
    if (t < 16) { mstat[t] = -1e30f; lstat[t] = 0.f; }

    float4 oa0 = make_float4(0.f, 0.f, 0.f, 0.f);
    float4 oa1 = make_float4(0.f, 0.f, 0.f, 0.f);
    const int qiA = (t >> 4) * 2;
    const int dA  = (t & 15);
    const int qiS = (t >> 5);
    const int kjS = (t & 31);

    for (int kb = 0; kb < 4; kb++) {
        __syncthreads();
        {
            const size_t baseK = ((size_t)(b * S_ + kb * 128)) * kpitch + hcol;
            #pragma unroll
            for (int it = 0; it < 16; it++) {
                int idx = t + it * 128;
                int r = idx >> 4, c4 = idx & 15;
                Buf[r * 17 + c4] =
                    *(const float4*)(Km + baseK + (size_t)r * kpitch + c4 * 4);
            }
        }
        __syncthreads();
        {
            float acc[4][4];
            #pragma unroll
            for (int qq = 0; qq < 4; qq++)
                #pragma unroll
                for (int kk = 0; kk < 4; kk++) acc[qq][kk] = 0.f;
            #pragma unroll
            for (int d4 = 0; d4 < 16; d4++) {
                float4 kv[4];
                #pragma unroll
                for (int kk = 0; kk < 4; kk++)
                    kv[kk] = Buf[(kjS + 32 * kk) * 17 + d4];
                #pragma unroll
                for (int qq = 0; qq < 4; qq++) {
                    float4 qv = Qs[qiS + 4 * qq][d4];
                    #pragma unroll
                    for (int kk = 0; kk < 4; kk++) {
                        acc[qq][kk] += qv.x * kv[kk].x + qv.y * kv[kk].y
                                     + qv.z * kv[kk].z + qv.w * kv[kk].w;
                    }
                }
            }
            #pragma unroll
            for (int qq = 0; qq < 4; qq++) {
                int qi = qiS + 4 * qq;
                int qg = q0g + qi;
                #pragma unroll
                for (int kk = 0; kk < 4; kk++) {
                    int kj = kjS + 32 * kk;
                    int kg = kb * 128 + kj;
                    float s = acc[qq][kk] * 0.125f;
                    if (kv_tok[b * S_ + kg] == 0) s += NEGV;
                    if (causal && kg > qg) s += NEGV;
                    Ssc[qi][kj] = s;
                }
            }
        }
        __syncthreads();
        {
            int row = t >> 3, l8 = t & 7;
            float mloc = -1e30f;
            #pragma unroll
            for (int c = 0; c < 16; c++)
                mloc = fmaxf(mloc, Ssc[row][l8 + 8 * c]);
            #pragma unroll
            for (int off = 4; off > 0; off >>= 1)
                mloc = fmaxf(mloc, __shfl_xor_sync(0xffffffffu, mloc, off));
            float m_old = mstat[row];
            float m_new = fmaxf(m_old, mloc);
            float ssum = 0.f;
            #pragma unroll
            for (int c = 0; c < 16; c++) {
                float p = expf(Ssc[row][l8 + 8 * c] - m_new);
                Ssc[row][l8 + 8 * c] = p;
                ssum += p;
            }
            #pragma unroll
            for (int off = 4; off > 0; off >>= 1)
                ssum += __shfl_xor_sync(0xffffffffu, ssum, off);
            if (l8 == 0) {
                float corr = expf(m_old - m_new);
                corrS[row] = corr;
                lstat[row] = lstat[row] * corr + ssum;
                mstat[row] = m_new;
            }
        }
        __syncthreads();
        {
            const size_t baseV = ((size_t)(b * S_ + kb * 128)) * kpitch + hcol;
            #pragma unroll
            for (int it = 0; it < 16; it++) {
                int idx = t + it * 128;
                int r = idx >> 4, c4 = idx & 15;
                Buf[r * 17 + c4] =
                    *(const float4*)(Vm + baseV + (size_t)r * kpitch + c4 * 4);
            }
        }
        __syncthreads();
        {
            float c0 = corrS[qiA], c1 = corrS[qiA + 1];
            oa0.x *= c0; oa0.y *= c0; oa0.z *= c0; oa0.w *= c0;
            oa1.x *= c1; oa1.y *= c1; oa1.z *= c1; oa1.w *= c1;
            #pragma unroll 4
            for (int kj = 0; kj < 128; kj++) {
                float p0 = Ssc[qiA][kj];
                float p1 = Ssc[qiA + 1][kj];
                float4 vv = Buf[kj * 17 + dA];
                oa0.x += p0 * vv.x; oa0.y += p0 * vv.y;
                oa0.z += p0 * vv.z; oa0.w += p0 * vv.w;
                oa1.x += p1 * vv.x; oa1.y += p1 * vv.y;
                oa1.z += p1 * vv.z; oa1.w += p1 * vv.w;
            }
        }
    }
    __syncthreads();
    {
        float inv0 = 1.f / lstat[qiA];
        float inv1 = 1.f / lstat[qiA + 1];
        float4 r0 = make_float4(oa0.x * inv0, oa0.y * inv0, oa0.z * inv0, oa0.w * inv0);
        float4 r1 = make_float4(oa1.x * inv1, oa1.y * inv1, oa1.z * inv1, oa1.w * inv1);
        size_t base0 = ((size_t)(b * S_ + q0g + qiA)) * D_ + hcol + dA * 4;
        size_t base1 = ((size_t)(b * S_ + q0g + qiA + 1)) * D_ + hcol + dA * 4;
        split_store4(Oh, Ol, base0, r0);
        split_store4(Oh, Ol, base1, r1);
    }
}

// ---------------------------------------------------------------------------
// Host driver
// ---------------------------------------------------------------------------
static inline void run_bgemm(int epi, const bf16* Ah, const bf16* Al,
                             const bf16* Bh, const bf16* Bl, const float* bias,
                             float* C, bf16* Ch, bf16* Cl, int M, int N, int K)
{
    dim3 grid(N / NT, M / 128);
    if (epi == 0)
        bgemm<0><<<grid, 256, SMEM_GEMM>>>(Ah, Al, Bh, Bl, bias, C, Ch, Cl, M, N, K);
    else if (epi == 1)
        bgemm<1><<<grid, 256, SMEM_GEMM>>>(Ah, Al, Bh, Bl, bias, C, Ch, Cl, M, N, K);
    else
        bgemm<3><<<grid, 256, SMEM_GEMM>>>(Ah, Al, Bh, Bl, bias, C, Ch, Cl, M, N, K);
}

extern "C" void kernel_launch(void* const* d_in, const int* in_sizes, int n_in,
                              void* d_out, int out_size)
{
    const int DDi  = D_ * D_;

    int iEWq, iEWk, iEWv, iEWo, iEW1, iEb1, iEW2, iEb2;
    int iDWq1, iDWk1, iDWv1, iDWo1, iDWq2, iDWk2, iDWv2, iDWo2;
    int iDW1, iDb1, iDW2, iDb2, iWout, iBout;
    if (n_in >= 8 && in_sizes[7] == L_ * DDi) {
        iEWq = 3; iEWk = 4; iEWv = 5; iEWo = 6;
        iDWq1 = 7; iDWk1 = 8; iDWv1 = 9; iDWo1 = 10;
        iDWq2 = 11; iDWk2 = 12; iDWv2 = 13; iDWo2 = 14;
        iEW1 = 15; iEb1 = 16; iEW2 = 17; iEb2 = 18;
        iDW1 = 19; iDb1 = 20; iDW2 = 21; iDb2 = 22;
        iWout = 23; iBout = 24;
    } else {
        iEWq = 3; iEWk = 4; iEWv = 5; iEWo = 6;
        iEW1 = 7; iEb1 = 8; iEW2 = 9; iEb2 = 10;
        iDWq1 = 11; iDWk1 = 12; iDWv1 = 13; iDWo1 = 14;
        iDWq2 = 15; iDWk2 = 16; iDWv2 = 17; iDWo2 = 18;
        iDW1 = 19; iDb1 = 20; iDW2 = 21; iDb2 = 22;
        iWout = 23; iBout = 24;
    }

    const int*   src  = (const int*)d_in[0];
    const int*   tgt  = (const int*)d_in[1];
    const float* emb  = (const float*)d_in[2];
    const float* eWq  = (const float*)d_in[iEWq];
    const float* eWk  = (const float*)d_in[iEWk];
    const float* eWv  = (const float*)d_in[iEWv];
    const float* eWo  = (const float*)d_in[iEWo];
    const float* eW1  = (const float*)d_in[iEW1];
    const float* eb1  = (const float*)d_in[iEb1];
    const float* eW2  = (const float*)d_in[iEW2];
    const float* eb2  = (const float*)d_in[iEb2];
    const float* dWq1 = (const float*)d_in[iDWq1];
    const float* dWk1 = (const float*)d_in[iDWk1];
    const float* dWv1 = (const float*)d_in[iDWv1];
    const float* dWo1 = (const float*)d_in[iDWo1];
    const float* dWq2 = (const float*)d_in[iDWq2];
    const float* dWk2 = (const float*)d_in[iDWk2];
    const float* dWv2 = (const float*)d_in[iDWv2];
    const float* dWo2 = (const float*)d_in[iDWo2];
    const float* dW1  = (const float*)d_in[iDW1];
    const float* db1  = (const float*)d_in[iDb1];
    const float* dW2  = (const float*)d_in[iDW2];
    const float* db2  = (const float*)d_in[iDb2];
    const float* Wout = (const float*)d_in[iWout];
    const float* bout = (const float*)d_in[iBout];

    cudaFuncSetAttribute(bgemm<0>, cudaFuncAttributeMaxDynamicSharedMemorySize, SMEM_GEMM);
    cudaFuncSetAttribute(bgemm<1>, cudaFuncAttributeMaxDynamicSharedMemorySize, SMEM_GEMM);
    cudaFuncSetAttribute(bgemm<3>, cudaFuncAttributeMaxDynamicSharedMemorySize, SMEM_GEMM);

    float *x, *q, *a, *out, *f, *y0, *o, *qkv, *kv2;
    cudaGetSymbolAddress((void**)&x,   g_x);
    cudaGetSymbolAddress((void**)&q,   g_q);
    cudaGetSymbolAddress((void**)&a,   g_a);
    cudaGetSymbolAddress((void**)&out, g_out);
    cudaGetSymbolAddress((void**)&f,   g_f);
    cudaGetSymbolAddress((void**)&y0,  g_y0);
    cudaGetSymbolAddress((void**)&o,   g_o);
    cudaGetSymbolAddress((void**)&qkv, g_qkv);
    cudaGetSymbolAddress((void**)&kv2, g_kv2);

    bf16 *xh, *xl, *outh, *outl, *ath, *atl, *y0h, *y0l, *oh, *ol, *hh, *hl, *wh, *wl;
    cudaGetSymbolAddress((void**)&xh,   g_xh);
    cudaGetSymbolAddress((void**)&xl,   g_xl);
    cudaGetSymbolAddress((void**)&outh, g_outh);
    cudaGetSymbolAddress((void**)&outl, g_outl);
    cudaGetSymbolAddress((void**)&ath,  g_ath);
    cudaGetSymbolAddress((void**)&atl,  g_atl);
    cudaGetSymbolAddress((void**)&y0h,  g_y0h);
    cudaGetSymbolAddress((void**)&y0l,  g_y0l);
    cudaGetSymbolAddress((void**)&oh,   g_oh);
    cudaGetSymbolAddress((void**)&ol,   g_ol);
    cudaGetSymbolAddress((void**)&hh,   g_hh);
    cudaGetSymbolAddress((void**)&hl,   g_hl);
    cudaGetSymbolAddress((void**)&wh,   g_wh);
    cudaGetSymbolAddress((void**)&wl,   g_wl);

    // ---- Weight conversion (transpose + bf16 split, fused-layout arena) ----
    dim3 blk(32, 8);
    const int li = L_ - 1;
    // encoder QKV fused per layer: [Wq;Wk;Wv], layer stride 3DD
    wconv_kernel<<<dim3(16, 16, 6), blk>>>(eWq, wh + O_EQKV,          wl + O_EQKV,          D_, D_, 3 * DD);
    wconv_kernel<<<dim3(16, 16, 6), blk>>>(eWk, wh + O_EQKV + DD,     wl + O_EQKV + DD,     D_, D_, 3 * DD);
    wconv_kernel<<<dim3(16, 16, 6), blk>>>(eWv, wh + O_EQKV + 2 * DD, wl + O_EQKV + 2 * DD, D_, D_, 3 * DD);
    wconv_kernel<<<dim3(16, 16, 6), blk>>>(eWo, wh + O_EWO, wl + O_EWO, D_, D_, DD);
    wconv_kernel<<<dim3(64, 16, 6), blk>>>(eW1, wh + O_EW1, wl + O_EW1, D_, DFF_, DDF);
    wconv_kernel<<<dim3(16, 64, 6), blk>>>(eW2, wh + O_EW2, wl + O_EW2, DFF_, D_, DDF);
    // decoder (last layer only)
    wconv_kernel<<<dim3(16, 16, 1), blk>>>(dWq1 + (size_t)li * DDi, wh + O_DQKV1,          wl + O_DQKV1,          D_, D_, 3 * DD);
    wconv_kernel<<<dim3(16, 16, 1), blk>>>(dWk1 + (size_t)li * DDi, wh + O_DQKV1 + DD,     wl + O_DQKV1 + DD,     D_, D_, 3 * DD);
    wconv_kernel<<<dim3(16, 16, 1), blk>>>(dWv1 + (size_t)li * DDi, wh + O_DQKV1 + 2 * DD, wl + O_DQKV1 + 2 * DD, D_, D_, 3 * DD);
    wconv_kernel<<<dim3(16, 16, 1), blk>>>(dWo1 + (size_t)li * DDi, wh + O_DWO1, wl + O_DWO1, D_, D_, DD);
    wconv_kernel<<<dim3(16, 16, 1), blk>>>(dWq2 + (size_t)li * DDi, wh + O_DWQ2, wl + O_DWQ2, D_, D_, DD);
    wconv_kernel<<<dim3(16, 16, 1), blk>>>(dWk2 + (size_t)li * DDi, wh + O_DKV2,      wl + O_DKV2,      D_, D_, 2 * DD);
    wconv_kernel<<<dim3(16, 16, 1), blk>>>(dWv2 + (size_t)li * DDi, wh + O_DKV2 + DD, wl + O_DKV2 + DD, D_, D_, 2 * DD);
    wconv_kernel<<<dim3(16, 16, 1), blk>>>(dWo2 + (size_t)li * DDi, wh + O_DWO2, wl + O_DWO2, D_, D_, DD);
    wconv_kernel<<<dim3(64, 16, 1), blk>>>(dW1 + (size_t)li * (D_ * DFF_), wh + O_DW1, wl + O_DW1, D_, DFF_, DDF);
    wconv_kernel<<<dim3(16, 64, 1), blk>>>(dW2 + (size_t)li * (D_ * DFF_), wh + O_DW2, wl + O_DW2, DFF_, D_, DDF);
    wconv_kernel<<<dim3(1000, 16, 1), blk>>>(Wout, wh + O_WOUT, wl + O_WOUT, D_, V_, (uint64_t)D_ * V_);

    const dim3 attnGrid(S_ / 16, H_, B_);

    // ---------------- Encoder ----------------
    embed_kernel<<<BS_, 128>>>(src, emb, x, xh, xl);
    for (int i = 0; i < L_; i++) {
        run_bgemm(0, xh, xl, wh + O_EQKV + (size_t)i * 3 * DD, wl + O_EQKV + (size_t)i * 3 * DD,
                  nullptr, qkv, nullptr, nullptr, BS_, 3 * D_, D_);
        attn_kernel<<<attnGrid, 128>>>(qkv, qkv + D_, qkv + 2 * D_, 3 * D_, 3 * D_,
                                       src, ath, atl, 0);
        run_bgemm(0, ath, atl, wh + O_EWO + (size_t)i * DD, wl + O_EWO + (size_t)i * DD,
                  nullptr, a, nullptr, nullptr, BS_, D_, D_);
        add_ln_kernel<<<BS_, 128>>>(x, a, out, outh, outl);
        run_bgemm(3, outh, outl, wh + O_EW1 + (size_t)i * DDF, wl + O_EW1 + (size_t)i * DDF,
                  eb1 + (size_t)i * DFF_, nullptr, hh, hl, BS_, DFF_, D_);
        run_bgemm(1, hh, hl, wh + O_EW2 + (size_t)i * DDF, wl + O_EW2 + (size_t)i * DDF,
                  eb2 + (size_t)i * D_, f, nullptr, nullptr, BS_, D_, DFF_);
        add_ln_kernel<<<BS_, 128>>>(a, f, x, xh, xl);
    }

    // ---------------- Decoder (last layer only) ----------------
    embed_kernel<<<BS_, 128>>>(tgt, emb, y0, y0h, y0l);
    {
        run_bgemm(0, y0h, y0l, wh + O_DQKV1, wl + O_DQKV1, nullptr, qkv,
                  nullptr, nullptr, BS_, 3 * D_, D_);
        attn_kernel<<<attnGrid, 128>>>(qkv, qkv + D_, qkv + 2 * D_, 3 * D_, 3 * D_,
                                       tgt, ath, atl, 1);
        run_bgemm(0, ath, atl, wh + O_DWO1, wl + O_DWO1, nullptr, a,
                  nullptr, nullptr, BS_, D_, D_);
        add_ln_kernel<<<BS_, 128>>>(y0, a, o, oh, ol);

        run_bgemm(0, oh, ol, wh + O_DWQ2, wl + O_DWQ2, nullptr, q,
                  nullptr, nullptr, BS_, D_, D_);
        run_bgemm(0, xh, xl, wh + O_DKV2, wl + O_DKV2, nullptr, kv2,
                  nullptr, nullptr, BS_, 2 * D_, D_);
        attn_kernel<<<attnGrid, 128>>>(q, kv2, kv2 + D_, D_, 2 * D_,
                                       src, ath, atl, 0);
        run_bgemm(0, ath, atl, wh + O_DWO2, wl + O_DWO2, nullptr, a,
                  nullptr, nullptr, BS_, D_, D_);
        add_ln_kernel<<<BS_, 128>>>(o, a, o, oh, ol);

        run_bgemm(3, oh, ol, wh + O_DW1, wl + O_DW1, db1 + (size_t)li * DFF_,
                  nullptr, hh, hl, BS_, DFF_, D_);
        run_bgemm(1, hh, hl, wh + O_DW2, wl + O_DW2, db2 + (size_t)li * D_,
                  f, nullptr, nullptr, BS_, D_, DFF_);
        add_ln_kernel<<<BS_, 128>>>(o, f, o, oh, ol);
    }

    // ---------------- Logits ----------------
    run_bgemm(1, oh, ol, wh + O_WOUT, wl + O_WOUT, bout, (float*)d_out,
              nullptr, nullptr, BS_, V_, D_);
}

// round 9
// speedup vs baseline: 3.3109x; 1.1739x over previous
#include <cuda_runtime.h>
#include <cuda_bf16.h>
#include <math.h>
#include <stdint.h>

#define D_    512
#define S_    512
#define B_    4
#define H_    8
#define L_    6
#define DFF_  2048
#define V_    32000
#define BS_   (B_ * S_)
#define NEGV  (-1e10f)

#if defined(__CUDA_ARCH_FEAT_SM103_ALL) || defined(__CUDA_ARCH_FEAT_SM100_ALL) || defined(__CUDA_ARCH_FEAT_SM101_ALL)
#define HAS_TC 1
#else
#define HAS_TC 0
#endif

typedef __nv_bfloat16  bf16;
typedef __nv_bfloat162 bf162;

// ---------------------------------------------------------------------------
// Scratch (device globals)
// ---------------------------------------------------------------------------
__device__ float g_x[BS_ * D_];
__device__ float g_a[BS_ * D_];
__device__ float g_out[BS_ * D_];
__device__ float g_f[BS_ * D_];
__device__ float g_y0[BS_ * D_];
__device__ float g_o[BS_ * D_];

__device__ bf16 g_xh[BS_ * D_],   g_xl[BS_ * D_];
__device__ bf16 g_outh[BS_ * D_], g_outl[BS_ * D_];
__device__ bf16 g_ath[BS_ * D_],  g_atl[BS_ * D_];
__device__ bf16 g_y0h[BS_ * D_],  g_y0l[BS_ * D_];
__device__ bf16 g_oh[BS_ * D_],   g_ol[BS_ * D_];
__device__ bf16 g_hh[BS_ * DFF_], g_hl[BS_ * DFF_];

// Attention scratch
__device__ bf16  g_qkvh[BS_ * 3 * D_], g_qkvl[BS_ * 3 * D_];   // fused QKV (pitch 1536)
__device__ bf16  g_kv2h[BS_ * 2 * D_], g_kv2l[BS_ * 2 * D_];   // cross K,V (pitch 1024)
__device__ bf16  g_q2h[BS_ * D_],      g_q2l[BS_ * D_];        // cross Q (pitch 512)
__device__ float g_scores[32ull * S_ * S_];                    // [b*H+h][q][k]
__device__ bf16  g_ph[32ull * S_ * S_], g_pl[32ull * S_ * S_]; // probs hi/lo
__device__ bf16  g_vth[32ull * 64 * S_], g_vtl[32ull * 64 * S_]; // V^T [z][d][tok]

// Transposed+split weights arena (element offsets). Per-layer-contiguous QKV.
#define DD      (512ull * 512ull)
#define DDF     (512ull * 2048ull)
#define O_EQKV  0ull
#define O_EWO   4718592ull
#define O_EW1   6291456ull
#define O_EW2   12582912ull
#define O_DQKV1 18874368ull
#define O_DWO1  19660800ull
#define O_DWQ2  19922944ull
#define O_DKV2  20185088ull
#define O_DWO2  20709376ull
#define O_DW1   20971520ull
#define O_DW2   22020096ull
#define O_WOUT  23068672ull
#define NWTOT   39452672ull
__device__ bf16 g_wh[NWTOT];
__device__ bf16 g_wl[NWTOT];

// ---------------------------------------------------------------------------
// PTX helpers
// ---------------------------------------------------------------------------
__device__ __forceinline__ uint32_t s2u(const void* p) {
    uint32_t a;
    asm("{ .reg .u64 t; cvta.to.shared.u64 t, %1; cvt.u32.u64 %0, t; }"
        : "=r"(a) : "l"(p));
    return a;
}
__device__ __forceinline__ uint32_t swz(uint32_t o) { return o ^ ((o >> 3) & 0x70u); }

__device__ __forceinline__ void mbar_init(uint32_t a, uint32_t c) {
    asm volatile("mbarrier.init.shared.b64 [%0], %1;" :: "r"(a), "r"(c) : "memory");
}
__device__ __forceinline__ void mbar_wait(uint32_t a, uint32_t ph) {
    uint32_t done;
    asm volatile(
        "{\n\t.reg .pred p;\n\t"
        "mbarrier.try_wait.parity.acquire.cta.shared::cta.b64 p, [%1], %2;\n\t"
        "selp.b32 %0,1,0,p;\n\t}"
        : "=r"(done) : "r"(a), "r"(ph) : "memory");
    if (!done) {
        asm volatile(
            "{\n\t.reg .pred P1;\n\t"
            "WAIT_LOOP_%=:\n\t"
            "mbarrier.try_wait.parity.acquire.cta.shared::cta.b64 P1, [%0], %1, 0x989680;\n\t"
            "@P1 bra.uni WAIT_DONE_%=;\n\t"
            "bra.uni WAIT_LOOP_%=;\n\t"
            "WAIT_DONE_%=:\n\t}"
            :: "r"(a), "r"(ph) : "memory");
    }
}
#define FENCE_ASYNC() asm volatile("fence.proxy.async.shared::cta;" ::: "memory")

__device__ __forceinline__ void cpasync16(uint32_t saddr, const void* g) {
    asm volatile("cp.async.cg.shared.global [%0], [%1], 16;"
                 :: "r"(saddr), "l"(g));
}
#define CP_COMMIT() asm volatile("cp.async.commit_group;" ::: "memory")
#define CP_WAIT1()  asm volatile("cp.async.wait_group 1;" ::: "memory")
#define CP_WAIT0()  asm volatile("cp.async.wait_group 0;" ::: "memory")

#if HAS_TC
__device__ __forceinline__ uint64_t mkdesc(uint32_t addr) {
    const uint64_t base = (2ull << 61) | (1ull << 46) | (64ull << 32) | (1ull << 16);
    return base | ((uint64_t)(addr >> 4) & 0x3FFFull);
}
__device__ __forceinline__ void mma_f16_ss(uint32_t d, uint64_t ad, uint64_t bd,
                                           uint32_t idesc, uint32_t en) {
    asm volatile(
        "{\n\t.reg .pred p;\n\tsetp.ne.u32 p, %5, 0;\n\t"
        "tcgen05.mma.cta_group::1.kind::f16 [%0], %1, %2, %3, {%4,%4,%4,%4}, p;\n\t}"
        :: "r"(d), "l"(ad), "l"(bd), "r"(idesc), "r"(0u), "r"(en) : "memory");
}
#define TC_ALLOC(sa, n)  asm volatile("tcgen05.alloc.cta_group::1.sync.aligned.shared::cta.b32 [%0], %1;" :: "r"(sa), "r"(n) : "memory")
#define TC_DEALLOC(t, n) asm volatile("tcgen05.dealloc.cta_group::1.sync.aligned.b32 %0, %1;" :: "r"(t), "r"(n))
#define TC_COMMIT(mb)    asm volatile("tcgen05.commit.cta_group::1.mbarrier::arrive::one.shared::cluster.b64 [%0];" :: "r"(mb) : "memory")
#define TC_FENCE_AFTER() asm volatile("tcgen05.fence::after_thread_sync;" ::: "memory")
#define TC_WAIT_LD()     asm volatile("tcgen05.wait::ld.sync.aligned;" ::: "memory")

#define TCLD32(r, a) \
    asm volatile( \
        "tcgen05.ld.sync.aligned.32x32b.x32.b32 " \
        "{%0, %1, %2, %3, %4, %5, %6, %7, " \
        " %8, %9, %10, %11, %12, %13, %14, %15, " \
        " %16, %17, %18, %19, %20, %21, %22, %23, " \
        " %24, %25, %26, %27, %28, %29, %30, %31}, [%32];" \
        : "=r"((r)[0]),  "=r"((r)[1]),  "=r"((r)[2]),  "=r"((r)[3]), \
          "=r"((r)[4]),  "=r"((r)[5]),  "=r"((r)[6]),  "=r"((r)[7]), \
          "=r"((r)[8]),  "=r"((r)[9]),  "=r"((r)[10]), "=r"((r)[11]), \
          "=r"((r)[12]), "=r"((r)[13]), "=r"((r)[14]), "=r"((r)[15]), \
          "=r"((r)[16]), "=r"((r)[17]), "=r"((r)[18]), "=r"((r)[19]), \
          "=r"((r)[20]), "=r"((r)[21]), "=r"((r)[22]), "=r"((r)[23]), \
          "=r"((r)[24]), "=r"((r)[25]), "=r"((r)[26]), "=r"((r)[27]), \
          "=r"((r)[28]), "=r"((r)[29]), "=r"((r)[30]), "=r"((r)[31]) \
        : "r"(a))
#endif  // HAS_TC

#define IDESC_N(n) ((1u<<4)|(1u<<7)|(1u<<10)|(((n)/8u)<<17)|(8u<<24))

__device__ __forceinline__ void split_store4(bf16* __restrict__ Hh,
                                             bf16* __restrict__ Hl,
                                             size_t idx, float4 v) {
    bf16 hx = __float2bfloat16_rn(v.x), hy = __float2bfloat16_rn(v.y);
    bf16 hz = __float2bfloat16_rn(v.z), hw = __float2bfloat16_rn(v.w);
    bf16 lx = __float2bfloat16_rn(v.x - __bfloat162float(hx));
    bf16 ly = __float2bfloat16_rn(v.y - __bfloat162float(hy));
    bf16 lz = __float2bfloat16_rn(v.z - __bfloat162float(hz));
    bf16 lw = __float2bfloat16_rn(v.w - __bfloat162float(hw));
    bf162 p;
    p.x = hx; p.y = hy; *(bf162*)(Hh + idx)     = p;
    p.x = hz; p.y = hw; *(bf162*)(Hh + idx + 2) = p;
    p.x = lx; p.y = ly; *(bf162*)(Hl + idx)     = p;
    p.x = lz; p.y = lw; *(bf162*)(Hl + idx + 2) = p;
}

// ---------------------------------------------------------------------------
// Weight transpose + bf16 split
// ---------------------------------------------------------------------------
__global__ __launch_bounds__(256) void wconv_kernel(
    const float* __restrict__ W, bf16* __restrict__ oh, bf16* __restrict__ ol,
    int K, int N, uint64_t lstride)
{
    __shared__ float tile[32][33];
    const int tx = threadIdx.x, ty = threadIdx.y;
    const int n0 = blockIdx.x * 32, k0 = blockIdx.y * 32, bz = blockIdx.z;
    const float* Wb = W + (size_t)bz * K * N;
    bf16* ohb = oh + (size_t)bz * lstride;
    bf16* olb = ol + (size_t)bz * lstride;
    #pragma unroll
    for (int i = 0; i < 4; i++)
        tile[ty + 8 * i][tx] = Wb[(size_t)(k0 + ty + 8 * i) * N + n0 + tx];
    __syncthreads();
    #pragma unroll
    for (int i = 0; i < 4; i++) {
        float v = tile[tx][ty + 8 * i];
        int n = n0 + ty + 8 * i, k = k0 + tx;
        size_t idx = (size_t)n * K + k;
        bf16 h = __float2bfloat16_rn(v);
        ohb[idx] = h;
        olb[idx] = __float2bfloat16_rn(v - __bfloat162float(h));
    }
}

// ---------------------------------------------------------------------------
// Embedding + positional encoding (+ bf16 split)
// ---------------------------------------------------------------------------
__global__ __launch_bounds__(128) void embed_kernel(
    const int* __restrict__ ids, const float* __restrict__ emb,
    float* __restrict__ out, bf16* __restrict__ oh, bf16* __restrict__ ol)
{
    const int row = blockIdx.x;
    const int s   = row & (S_ - 1);
    const int tok = ids[row];
    const int t   = threadIdx.x;
    const float c = -logf(10000.0f) / (float)D_;
    float4 v;
    float tmp[4];
    #pragma unroll
    for (int j = 0; j < 4; j++) {
        int d  = t * 4 + j;
        int tj = d >> 1;
        float div = expf((float)(2 * tj) * c);
        float ang = (float)s * div;
        float pe  = (d & 1) ? cosf(ang) : sinf(ang);
        tmp[j] = emb[(size_t)tok * D_ + d] + pe;
    }
    v.x = tmp[0]; v.y = tmp[1]; v.z = tmp[2]; v.w = tmp[3];
    size_t base = (size_t)row * D_ + t * 4;
    *(float4*)(out + base) = v;
    split_store4(oh, ol, base, v);
}

// ---------------------------------------------------------------------------
// Fused residual + LayerNorm (+ bf16 split)
// ---------------------------------------------------------------------------
__global__ __launch_bounds__(128) void add_ln_kernel(
    const float* __restrict__ A, const float* __restrict__ Bv,
    float* __restrict__ Out, bf16* __restrict__ Oh, bf16* __restrict__ Ol)
{
    const int row = blockIdx.x;
    const int t   = threadIdx.x;
    const size_t base = (size_t)row * D_ + t * 4;
    float4 a = *(const float4*)(A + base);
    float4 b = *(const float4*)(Bv + base);
    float4 vv;
    vv.x = a.x + b.x; vv.y = a.y + b.y; vv.z = a.z + b.z; vv.w = a.w + b.w;

    float s  = vv.x + vv.y + vv.z + vv.w;
    float sq = vv.x * vv.x + vv.y * vv.y + vv.z * vv.z + vv.w * vv.w;
    __shared__ float redS[4], redQ[4];
    #pragma unroll
    for (int off = 16; off > 0; off >>= 1) {
        s  += __shfl_xor_sync(0xffffffffu, s,  off);
        sq += __shfl_xor_sync(0xffffffffu, sq, off);
    }
    const int wid = t >> 5, lane = t & 31;
    if (lane == 0) { redS[wid] = s; redQ[wid] = sq; }
    __syncthreads();
    s  = redS[0] + redS[1] + redS[2] + redS[3];
    sq = redQ[0] + redQ[1] + redQ[2] + redQ[3];
    float mean = s * (1.0f / D_);
    float var  = sq * (1.0f / D_) - mean * mean;
    float inv  = rsqrtf(var + 1e-5f);
    float4 o;
    o.x = (vv.x - mean) * inv; o.y = (vv.y - mean) * inv;
    o.z = (vv.z - mean) * inv; o.w = (vv.w - mean) * inv;
    *(float4*)(Out + base) = o;
    split_store4(Oh, Ol, base, o);
}

// ---------------------------------------------------------------------------
// tcgen05 split-fp32 GEMM (weights), 3-stage cp.async pipeline.
// EPI: 0 none->C ; 1 +bias->C ; 3 +bias+relu->hi/lo ; 4 split->hi/lo
// ---------------------------------------------------------------------------
#define NT        128
#define GIDESC    IDESC_N(128)
#define STAGE_B   65536
#define NSTG      3
#define SMEM_GEMM (NSTG * STAGE_B + 1024)

template<int EPI>
__global__ __launch_bounds__(256)
void bgemm(const bf16* __restrict__ Ah, const bf16* __restrict__ Al,
           const bf16* __restrict__ Bh, const bf16* __restrict__ Bl,
           const float* __restrict__ bias, float* __restrict__ C,
           bf16* __restrict__ Ch, bf16* __restrict__ Cl,
           int M, int N, int K)
{
#if HAS_TC
    __shared__ __align__(16) uint32_t s_tptr[4];
    __shared__ __align__(16) uint64_t s_mbar[NSTG];
    extern __shared__ char smem[];
    const uint32_t tiles = (s2u(smem) + 1023u) & ~1023u;
    const uint32_t tptr  = s2u(s_tptr);
    uint32_t mb[NSTG];
    #pragma unroll
    for (int i = 0; i < NSTG; i++) mb[i] = s2u(&s_mbar[i]);

    const int t   = threadIdx.x;
    const int wid = t >> 5;
    const int bm  = blockIdx.y * 128, bn = blockIdx.x * NT;

    if (wid == 0) TC_ALLOC(tptr, 128);
    if (t == 0) {
        #pragma unroll
        for (int i = 0; i < NSTG; i++) mbar_init(mb[i], 1);
    }
    __syncthreads();
    const uint32_t tmem = s_tptr[0];

    const int r  = t >> 3;
    const int ck = t & 7;
    const int nch = K >> 6;
    int use[NSTG];
    #pragma unroll
    for (int i = 0; i < NSTG; i++) use[i] = 0;

    auto load_chunk = [&](int c, int s) {
        const uint32_t base = tiles + s * STAGE_B;
        const uint32_t aH = base, aL = base + 16384;
        const uint32_t bH = base + 32768, bL = base + 49152;
        const int k0 = c << 6;
        #pragma unroll
        for (int it = 0; it < 4; it++) {
            int row = r + it * 32;
            size_t g = (size_t)(bm + row) * K + k0 + ck * 8;
            uint32_t so = swz((uint32_t)(row * 128 + ck * 16));
            cpasync16(aH + so, Ah + g);
            cpasync16(aL + so, Al + g);
        }
        #pragma unroll
        for (int it = 0; it < 4; it++) {
            int row = r + it * 32;
            size_t g = (size_t)(bn + row) * K + k0 + ck * 8;
            uint32_t so = swz((uint32_t)(row * 128 + ck * 16));
            cpasync16(bH + so, Bh + g);
            cpasync16(bL + so, Bl + g);
        }
        CP_COMMIT();
    };

    load_chunk(0, 0);
    for (int c = 0; c < nch; c++) {
        const int s = c % NSTG;
        if (c + 1 < nch) {
            const int s2 = (c + 1) % NSTG;
            if (use[s2] > 0) mbar_wait(mb[s2], (use[s2] - 1) & 1);
            load_chunk(c + 1, s2);
            CP_WAIT1();
        } else {
            CP_WAIT0();
        }
        FENCE_ASYNC();
        __syncthreads();
        if (t == 0) {
            const uint32_t base = tiles + s * STAGE_B;
            uint64_t dah = mkdesc(base),         dal = mkdesc(base + 16384);
            uint64_t dbh = mkdesc(base + 32768), dbl = mkdesc(base + 49152);
            #pragma unroll
            for (int j = 0; j < 4; j++)
                mma_f16_ss(tmem, dah + 2 * j, dbh + 2 * j, GIDESC,
                           (c == 0 && j == 0) ? 0u : 1u);
            #pragma unroll
            for (int j = 0; j < 4; j++)
                mma_f16_ss(tmem, dah + 2 * j, dbl + 2 * j, GIDESC, 1u);
            #pragma unroll
            for (int j = 0; j < 4; j++)
                mma_f16_ss(tmem, dal + 2 * j, dbh + 2 * j, GIDESC, 1u);
            TC_COMMIT(mb[s]);
        }
        use[s]++;
    }
    #pragma unroll
    for (int i = 0; i < NSTG; i++)
        if (use[i] > 0) mbar_wait(mb[i], (use[i] - 1) & 1);
    TC_FENCE_AFTER();

    {
        const int sub = wid & 3, half = wid >> 2, lane = t & 31;
        const int rowg = bm + sub * 32 + lane;
        #pragma unroll
        for (int cc = 0; cc < 2; cc++) {
            const int col0 = half * 64 + cc * 32;
            uint32_t regs[32];
            TCLD32(regs, tmem + col0);
            TC_WAIT_LD();
            if (EPI == 0) {
                #pragma unroll
                for (int j = 0; j < 32; j += 4) {
                    float4 v;
                    v.x = __uint_as_float(regs[j]);
                    v.y = __uint_as_float(regs[j + 1]);
                    v.z = __uint_as_float(regs[j + 2]);
                    v.w = __uint_as_float(regs[j + 3]);
                    *(float4*)(C + (size_t)rowg * N + bn + col0 + j) = v;
                }
            } else if (EPI == 1) {
                #pragma unroll
                for (int j = 0; j < 32; j += 4) {
                    float4 bv = *(const float4*)(bias + bn + col0 + j);
                    float4 v;
                    v.x = __uint_as_float(regs[j])     + bv.x;
                    v.y = __uint_as_float(regs[j + 1]) + bv.y;
                    v.z = __uint_as_float(regs[j + 2]) + bv.z;
                    v.w = __uint_as_float(regs[j + 3]) + bv.w;
                    *(float4*)(C + (size_t)rowg * N + bn + col0 + j) = v;
                }
            } else if (EPI == 3) {
                #pragma unroll
                for (int j = 0; j < 32; j += 4) {
                    float4 bv = *(const float4*)(bias + bn + col0 + j);
                    float4 v;
                    v.x = fmaxf(__uint_as_float(regs[j])     + bv.x, 0.f);
                    v.y = fmaxf(__uint_as_float(regs[j + 1]) + bv.y, 0.f);
                    v.z = fmaxf(__uint_as_float(regs[j + 2]) + bv.z, 0.f);
                    v.w = fmaxf(__uint_as_float(regs[j + 3]) + bv.w, 0.f);
                    split_store4(Ch, Cl, (size_t)rowg * N + bn + col0 + j, v);
                }
            } else {  // EPI == 4: split only
                #pragma unroll
                for (int j = 0; j < 32; j += 4) {
                    float4 v;
                    v.x = __uint_as_float(regs[j]);
                    v.y = __uint_as_float(regs[j + 1]);
                    v.z = __uint_as_float(regs[j + 2]);
                    v.w = __uint_as_float(regs[j + 3]);
                    split_store4(Ch, Cl, (size_t)rowg * N + bn + col0 + j, v);
                }
            }
        }
    }
    __syncthreads();
    if (wid == 0) TC_DEALLOC(tmem, 128);
#else
    const int t  = threadIdx.x;
    const int bm = blockIdx.y * 128, bn = blockIdx.x * NT;
    const int r0 = (t >> 4) * 8;
    const int c0 = (t & 15) * 8;
    float acc[8][8];
    #pragma unroll
    for (int i = 0; i < 8; i++)
        #pragma unroll
        for (int j = 0; j < 8; j++) acc[i][j] = 0.f;
    for (int k = 0; k < K; k++) {
        float av[8], bv[8];
        #pragma unroll
        for (int i = 0; i < 8; i++) {
            size_t ga = (size_t)(bm + r0 + i) * K + k;
            av[i] = __bfloat162float(Ah[ga]) + __bfloat162float(Al[ga]);
            size_t gb = (size_t)(bn + c0 + i) * K + k;
            bv[i] = __bfloat162float(Bh[gb]) + __bfloat162float(Bl[gb]);
        }
        #pragma unroll
        for (int i = 0; i < 8; i++)
            #pragma unroll
            for (int j = 0; j < 8; j++)
                acc[i][j] += av[i] * bv[j];
    }
    #pragma unroll
    for (int i = 0; i < 8; i++)
        #pragma unroll
        for (int j = 0; j < 8; j++) {
            float v = acc[i][j];
            if (EPI == 1 || EPI == 3) v += bias[bn + c0 + j];
            if (EPI == 3) v = fmaxf(v, 0.f);
            size_t idx = (size_t)(bm + r0 + i) * N + bn + c0 + j;
            if (EPI == 3 || EPI == 4) {
                bf16 h = __float2bfloat16_rn(v);
                Ch[idx] = h;
                Cl[idx] = __float2bfloat16_rn(v - __bfloat162float(h));
            } else {
                C[idx] = v;
            }
        }
#endif
}

// ---------------------------------------------------------------------------
// QK^T GEMM: scores[z][q][k] = 0.125 * Q[z,q,:64] . K[z,k,:64], split bf16.
// Grid (4, 4, 32), 256 thr. Single K-chunk (64 bf16 = one SW128 row).
// ---------------------------------------------------------------------------
#define QK_SMEM (65536 + 1024)
__global__ __launch_bounds__(256) void qk_gemm(
    const bf16* __restrict__ Qh, const bf16* __restrict__ Ql, int qp,
    const bf16* __restrict__ Kh, const bf16* __restrict__ Kl, int kp,
    float* __restrict__ scores)
{
    const int z = blockIdx.z, b = z >> 3, h = z & 7;
    const int bm = blockIdx.y * 128, bn = blockIdx.x * 128;
    const size_t qoff = (size_t)(b * S_) * qp + h * 64;
    const size_t koff = (size_t)(b * S_) * kp + h * 64;
#if HAS_TC
    __shared__ __align__(16) uint32_t s_tptr[4];
    __shared__ __align__(16) uint64_t s_mbar[1];
    extern __shared__ char smem[];
    const uint32_t tiles = (s2u(smem) + 1023u) & ~1023u;
    const uint32_t tptr  = s2u(s_tptr);
    const uint32_t mb    = s2u(&s_mbar[0]);

    const int t   = threadIdx.x;
    const int wid = t >> 5;
    if (wid == 0) TC_ALLOC(tptr, 128);
    if (t == 0) mbar_init(mb, 1);
    __syncthreads();
    const uint32_t tmem = s_tptr[0];

    const int r  = t >> 3;
    const int ck = t & 7;
    const uint32_t aH = tiles, aL = tiles + 16384;
    const uint32_t bH = tiles + 32768, bL = tiles + 49152;
    #pragma unroll
    for (int it = 0; it < 4; it++) {
        int row = r + it * 32;
        uint32_t so = swz((uint32_t)(row * 128 + ck * 16));
        cpasync16(aH + so, Qh + qoff + (size_t)(bm + row) * qp + ck * 8);
        cpasync16(aL + so, Ql + qoff + (size_t)(bm + row) * qp + ck * 8);
        cpasync16(bH + so, Kh + koff + (size_t)(bn + row) * kp + ck * 8);
        cpasync16(bL + so, Kl + koff + (size_t)(bn + row) * kp + ck * 8);
    }
    CP_COMMIT(); CP_WAIT0();
    FENCE_ASYNC();
    __syncthreads();
    if (t == 0) {
        uint64_t dah = mkdesc(aH), dal = mkdesc(aL);
        uint64_t dbh = mkdesc(bH), dbl = mkdesc(bL);
        #pragma unroll
        for (int j = 0; j < 4; j++)
            mma_f16_ss(tmem, dah + 2 * j, dbh + 2 * j, GIDESC, j ? 1u : 0u);
        #pragma unroll
        for (int j = 0; j < 4; j++)
            mma_f16_ss(tmem, dah + 2 * j, dbl + 2 * j, GIDESC, 1u);
        #pragma unroll
        for (int j = 0; j < 4; j++)
            mma_f16_ss(tmem, dal + 2 * j, dbh + 2 * j, GIDESC, 1u);
        TC_COMMIT(mb);
    }
    mbar_wait(mb, 0);
    TC_FENCE_AFTER();
    {
        const int sub = wid & 3, half = wid >> 2, lane = t & 31;
        const int rowg = bm + sub * 32 + lane;
        float* out = scores + ((size_t)z * S_ + rowg) * S_;
        #pragma unroll
        for (int cc = 0; cc < 2; cc++) {
            const int col0 = half * 64 + cc * 32;
            uint32_t regs[32];
            TCLD32(regs, tmem + col0);
            TC_WAIT_LD();
            #pragma unroll
            for (int j = 0; j < 32; j += 4) {
                float4 v;
                v.x = __uint_as_float(regs[j])     * 0.125f;
                v.y = __uint_as_float(regs[j + 1]) * 0.125f;
                v.z = __uint_as_float(regs[j + 2]) * 0.125f;
                v.w = __uint_as_float(regs[j + 3]) * 0.125f;
                *(float4*)(out + bn + col0 + j) = v;
            }
        }
    }
    __syncthreads();
    if (wid == 0) TC_DEALLOC(tmem, 128);
#else
    const int t = threadIdx.x;
    for (int idx = t; idx < 128 * 128; idx += 256) {
        int rr = idx >> 7, cc = idx & 127;
        float acc = 0.f;
        for (int k = 0; k < 64; k++) {
            float qv = __bfloat162float(Qh[qoff + (size_t)(bm + rr) * qp + k])
                     + __bfloat162float(Ql[qoff + (size_t)(bm + rr) * qp + k]);
            float kv = __bfloat162float(Kh[koff + (size_t)(bn + cc) * kp + k])
                     + __bfloat162float(Kl[koff + (size_t)(bn + cc) * kp + k]);
            acc += qv * kv;
        }
        scores[((size_t)z * S_ + bm + rr) * S_ + bn + cc] = acc * 0.125f;
    }
#endif
}

// ---------------------------------------------------------------------------
// Masked softmax over scores row -> P hi/lo. Grid (512, 32), 128 thr.
// ---------------------------------------------------------------------------
__global__ __launch_bounds__(128) void softmax_kernel(
    const float* __restrict__ scores, const int* __restrict__ kv_tok,
    bf16* __restrict__ Ph, bf16* __restrict__ Pl, int causal)
{
    const int q = blockIdx.x, z = blockIdx.y, b = z >> 3;
    const int t = threadIdx.x;
    const size_t base = ((size_t)z * S_ + q) * S_;
    float4 s = *(const float4*)(scores + base + t * 4);
    float vals[4] = {s.x, s.y, s.z, s.w};
    #pragma unroll
    for (int j = 0; j < 4; j++) {
        int k = t * 4 + j;
        if (kv_tok[b * S_ + k] == 0) vals[j] += NEGV;
        if (causal && k > q)         vals[j] += NEGV;
    }
    float m = fmaxf(fmaxf(vals[0], vals[1]), fmaxf(vals[2], vals[3]));
    __shared__ float redM[4], redS[4];
    #pragma unroll
    for (int off = 16; off > 0; off >>= 1)
        m = fmaxf(m, __shfl_xor_sync(0xffffffffu, m, off));
    const int wid = t >> 5, lane = t & 31;
    if (lane == 0) redM[wid] = m;
    __syncthreads();
    m = fmaxf(fmaxf(redM[0], redM[1]), fmaxf(redM[2], redM[3]));

    float e[4], ssum = 0.f;
    #pragma unroll
    for (int j = 0; j < 4; j++) { e[j] = __expf(vals[j] - m); ssum += e[j]; }
    #pragma unroll
    for (int off = 16; off > 0; off >>= 1)
        ssum += __shfl_xor_sync(0xffffffffu, ssum, off);
    if (lane == 0) redS[wid] = ssum;
    __syncthreads();
    ssum = redS[0] + redS[1] + redS[2] + redS[3];
    float inv = 1.f / ssum;
    float4 p = make_float4(e[0] * inv, e[1] * inv, e[2] * inv, e[3] * inv);
    split_store4(Ph, Pl, base + t * 4, p);
}

// ---------------------------------------------------------------------------
// V transpose: V[b,tok, h*64+d] (hi/lo, pitch) -> vt[z][d][tok] hi/lo
// Grid (16, 2, 32), block (32, 8)
// ---------------------------------------------------------------------------
__global__ __launch_bounds__(256) void vt_kernel(
    const bf16* __restrict__ Vh, const bf16* __restrict__ Vl, int pitch,
    bf16* __restrict__ vth, bf16* __restrict__ vtl)
{
    __shared__ bf16 th[32][33], tl[32][33];
    const int tx = threadIdx.x, ty = threadIdx.y;
    const int t0 = blockIdx.x * 32, d0 = blockIdx.y * 32;
    const int z = blockIdx.z, b = z >> 3, h = z & 7;
    const size_t ibase = (size_t)(b * S_) * pitch + h * 64;
    #pragma unroll
    for (int i = 0; i < 4; i++) {
        int tok = t0 + ty + 8 * i;
        th[ty + 8 * i][tx] = Vh[ibase + (size_t)tok * pitch + d0 + tx];
        tl[ty + 8 * i][tx] = Vl[ibase + (size_t)tok * pitch + d0 + tx];
    }
    __syncthreads();
    const size_t obase = (size_t)z * 64 * S_;
    #pragma unroll
    for (int i = 0; i < 4; i++) {
        int d = d0 + ty + 8 * i, tok = t0 + tx;
        vth[obase + (size_t)d * S_ + tok] = th[tx][ty + 8 * i];
        vtl[obase + (size_t)d * S_ + tok] = tl[tx][ty + 8 * i];
    }
}

// ---------------------------------------------------------------------------
// AV GEMM: out[z][q][d] = sum_k P[z,q,k] * Vt[z,d,k]; M=512, N=64, K=512.
// Split-store into attention-output hi/lo at [(b*S+q)*512 + h*64 + d].
// Grid (1, 4, 32), 256 thr, 3-stage cp.async pipeline.
// ---------------------------------------------------------------------------
#define AV_STAGE  49152
#define AV_SMEM   (NSTG * AV_STAGE + 1024)
#define AVIDESC   IDESC_N(64)
__global__ __launch_bounds__(256) void av_gemm(
    const bf16* __restrict__ Ph, const bf16* __restrict__ Pl,
    const bf16* __restrict__ Vth, const bf16* __restrict__ Vtl,
    bf16* __restrict__ Oh, bf16* __restrict__ Ol)
{
    const int z = blockIdx.z, b = z >> 3, h = z & 7;
    const int bm = blockIdx.y * 128;
    const bf16* Pzh = Ph  + (size_t)z * S_ * S_;
    const bf16* Pzl = Pl  + (size_t)z * S_ * S_;
    const bf16* Vzh = Vth + (size_t)z * 64 * S_;
    const bf16* Vzl = Vtl + (size_t)z * 64 * S_;
#if HAS_TC
    __shared__ __align__(16) uint32_t s_tptr[4];
    __shared__ __align__(16) uint64_t s_mbar[NSTG];
    extern __shared__ char smem[];
    const uint32_t tiles = (s2u(smem) + 1023u) & ~1023u;
    const uint32_t tptr  = s2u(s_tptr);
    uint32_t mb[NSTG];
    #pragma unroll
    for (int i = 0; i < NSTG; i++) mb[i] = s2u(&s_mbar[i]);

    const int t   = threadIdx.x;
    const int wid = t >> 5;
    if (wid == 0) TC_ALLOC(tptr, 128);
    if (t == 0) {
        #pragma unroll
        for (int i = 0; i < NSTG; i++) mbar_init(mb[i], 1);
    }
    __syncthreads();
    const uint32_t tmem = s_tptr[0];

    const int r  = t >> 3;
    const int ck = t & 7;
    int use[NSTG];
    #pragma unroll
    for (int i = 0; i < NSTG; i++) use[i] = 0;

    auto load_chunk = [&](int c, int s) {
        const uint32_t base = tiles + s * AV_STAGE;
        const uint32_t aH = base, aL = base + 16384;
        const uint32_t bH = base + 32768, bL = base + 40960;
        const int k0 = c << 6;
        #pragma unroll
        for (int it = 0; it < 4; it++) {
            int row = r + it * 32;
            size_t g = (size_t)(bm + row) * S_ + k0 + ck * 8;
            uint32_t so = swz((uint32_t)(row * 128 + ck * 16));
            cpasync16(aH + so, Pzh + g);
            cpasync16(aL + so, Pzl + g);
        }
        #pragma unroll
        for (int it = 0; it < 2; it++) {
            int row = r + it * 32;
            size_t g = (size_t)row * S_ + k0 + ck * 8;
            uint32_t so = swz((uint32_t)(row * 128 + ck * 16));
            cpasync16(bH + so, Vzh + g);
            cpasync16(bL + so, Vzl + g);
        }
        CP_COMMIT();
    };

    const int nch = S_ >> 6;   // 8
    load_chunk(0, 0);
    for (int c = 0; c < nch; c++) {
        const int s = c % NSTG;
        if (c + 1 < nch) {
            const int s2 = (c + 1) % NSTG;
            if (use[s2] > 0) mbar_wait(mb[s2], (use[s2] - 1) & 1);
            load_chunk(c + 1, s2);
            CP_WAIT1();
        } else {
            CP_WAIT0();
        }
        FENCE_ASYNC();
        __syncthreads();
        if (t == 0) {
            const uint32_t base = tiles + s * AV_STAGE;
            uint64_t dah = mkdesc(base),         dal = mkdesc(base + 16384);
            uint64_t dbh = mkdesc(base + 32768), dbl = mkdesc(base + 40960);
            #pragma unroll
            for (int j = 0; j < 4; j++)
                mma_f16_ss(tmem, dah + 2 * j, dbh + 2 * j, AVIDESC,
                           (c == 0 && j == 0) ? 0u : 1u);
            #pragma unroll
            for (int j = 0; j < 4; j++)
                mma_f16_ss(tmem, dah + 2 * j, dbl + 2 * j, AVIDESC, 1u);
            #pragma unroll
            for (int j = 0; j < 4; j++)
                mma_f16_ss(tmem, dal + 2 * j, dbh + 2 * j, AVIDESC, 1u);
            TC_COMMIT(mb[s]);
        }
        use[s]++;
    }
    #pragma unroll
    for (int i = 0; i < NSTG; i++)
        if (use[i] > 0) mbar_wait(mb[i], (use[i] - 1) & 1);
    TC_FENCE_AFTER();
    {
        const int sub = wid & 3, half = wid >> 2, lane = t & 31;
        const int rowg = bm + sub * 32 + lane;
        const int col0 = half * 32;
        uint32_t regs[32];
        TCLD32(regs, tmem + col0);
        TC_WAIT_LD();
        #pragma unroll
        for (int j = 0; j < 32; j += 4) {
            float4 v;
            v.x = __uint_as_float(regs[j]);
            v.y = __uint_as_float(regs[j + 1]);
            v.z = __uint_as_float(regs[j + 2]);
            v.w = __uint_as_float(regs[j + 3]);
            size_t idx = ((size_t)(b * S_) + rowg) * D_ + h * 64 + col0 + j;
            split_store4(Oh, Ol, idx, v);
        }
    }
    __syncthreads();
    if (wid == 0) TC_DEALLOC(tmem, 128);
#else
    const int t = threadIdx.x;
    for (int idx = t; idx < 128 * 64; idx += 256) {
        int rr = idx >> 6, cc = idx & 63;
        float acc = 0.f;
        for (int k = 0; k < S_; k++) {
            float pv = __bfloat162float(Pzh[(size_t)(bm + rr) * S_ + k])
                     + __bfloat162float(Pzl[(size_t)(bm + rr) * S_ + k]);
            float vv = __bfloat162float(Vzh[(size_t)cc * S_ + k])
                     + __bfloat162float(Vzl[(size_t)cc * S_ + k]);
            acc += pv * vv;
        }
        size_t oidx = ((size_t)(b * S_) + bm + rr) * D_ + h * 64 + cc;
        bf16 hh2 = __float2bfloat16_rn(acc);
        Oh[oidx] = hh2;
        Ol[oidx] = __float2bfloat16_rn(acc - __bfloat162float(hh2));
    }
#endif
}

// ---------------------------------------------------------------------------
// Host driver
// ---------------------------------------------------------------------------
static inline void run_bgemm(int epi, const bf16* Ah, const bf16* Al,
                             const bf16* Bh, const bf16* Bl, const float* bias,
                             float* C, bf16* Ch, bf16* Cl, int M, int N, int K)
{
    dim3 grid(N / NT, M / 128);
    if (epi == 0)
        bgemm<0><<<grid, 256, SMEM_GEMM>>>(Ah, Al, Bh, Bl, bias, C, Ch, Cl, M, N, K);
    else if (epi == 1)
        bgemm<1><<<grid, 256, SMEM_GEMM>>>(Ah, Al, Bh, Bl, bias, C, Ch, Cl, M, N, K);
    else if (epi == 3)
        bgemm<3><<<grid, 256, SMEM_GEMM>>>(Ah, Al, Bh, Bl, bias, C, Ch, Cl, M, N, K);
    else
        bgemm<4><<<grid, 256, SMEM_GEMM>>>(Ah, Al, Bh, Bl, bias, C, Ch, Cl, M, N, K);
}

extern "C" void kernel_launch(void* const* d_in, const int* in_sizes, int n_in,
                              void* d_out, int out_size)
{
    const int DDi = D_ * D_;

    int iEWq, iEWk, iEWv, iEWo, iEW1, iEb1, iEW2, iEb2;
    int iDWq1, iDWk1, iDWv1, iDWo1, iDWq2, iDWk2, iDWv2, iDWo2;
    int iDW1, iDb1, iDW2, iDb2, iWout, iBout;
    if (n_in >= 8 && in_sizes[7] == L_ * DDi) {
        iEWq = 3; iEWk = 4; iEWv = 5; iEWo = 6;
        iDWq1 = 7; iDWk1 = 8; iDWv1 = 9; iDWo1 = 10;
        iDWq2 = 11; iDWk2 = 12; iDWv2 = 13; iDWo2 = 14;
        iEW1 = 15; iEb1 = 16; iEW2 = 17; iEb2 = 18;
        iDW1 = 19; iDb1 = 20; iDW2 = 21; iDb2 = 22;
        iWout = 23; iBout = 24;
    } else {
        iEWq = 3; iEWk = 4; iEWv = 5; iEWo = 6;
        iEW1 = 7; iEb1 = 8; iEW2 = 9; iEb2 = 10;
        iDWq1 = 11; iDWk1 = 12; iDWv1 = 13; iDWo1 = 14;
        iDWq2 = 15; iDWk2 = 16; iDWv2 = 17; iDWo2 = 18;
        iDW1 = 19; iDb1 = 20; iDW2 = 21; iDb2 = 22;
        iWout = 23; iBout = 24;
    }

    const int*   src  = (const int*)d_in[0];
    const int*   tgt  = (const int*)d_in[1];
    const float* emb  = (const float*)d_in[2];
    const float* eWq  = (const float*)d_in[iEWq];
    const float* eWk  = (const float*)d_in[iEWk];
    const float* eWv  = (const float*)d_in[iEWv];
    const float* eWo  = (const float*)d_in[iEWo];
    const float* eW1  = (const float*)d_in[iEW1];
    const float* eb1  = (const float*)d_in[iEb1];
    const float* eW2  = (const float*)d_in[iEW2];
    const float* eb2  = (const float*)d_in[iEb2];
    const float* dWq1 = (const float*)d_in[iDWq1];
    const float* dWk1 = (const float*)d_in[iDWk1];
    const float* dWv1 = (const float*)d_in[iDWv1];
    const float* dWo1 = (const float*)d_in[iDWo1];
    const float* dWq2 = (const float*)d_in[iDWq2];
    const float* dWk2 = (const float*)d_in[iDWk2];
    const float* dWv2 = (const float*)d_in[iDWv2];
    const float* dWo2 = (const float*)d_in[iDWo2];
    const float* dW1  = (const float*)d_in[iDW1];
    const float* db1  = (const float*)d_in[iDb1];
    const float* dW2  = (const float*)d_in[iDW2];
    const float* db2  = (const float*)d_in[iDb2];
    const float* Wout = (const float*)d_in[iWout];
    const float* bout = (const float*)d_in[iBout];

    cudaFuncSetAttribute(bgemm<0>, cudaFuncAttributeMaxDynamicSharedMemorySize, SMEM_GEMM);
    cudaFuncSetAttribute(bgemm<1>, cudaFuncAttributeMaxDynamicSharedMemorySize, SMEM_GEMM);
    cudaFuncSetAttribute(bgemm<3>, cudaFuncAttributeMaxDynamicSharedMemorySize, SMEM_GEMM);
    cudaFuncSetAttribute(bgemm<4>, cudaFuncAttributeMaxDynamicSharedMemorySize, SMEM_GEMM);
    cudaFuncSetAttribute(qk_gemm,  cudaFuncAttributeMaxDynamicSharedMemorySize, QK_SMEM);
    cudaFuncSetAttribute(av_gemm,  cudaFuncAttributeMaxDynamicSharedMemorySize, AV_SMEM);

    float *x, *a, *out, *f, *y0, *o, *scores;
    cudaGetSymbolAddress((void**)&x,   g_x);
    cudaGetSymbolAddress((void**)&a,   g_a);
    cudaGetSymbolAddress((void**)&out, g_out);
    cudaGetSymbolAddress((void**)&f,   g_f);
    cudaGetSymbolAddress((void**)&y0,  g_y0);
    cudaGetSymbolAddress((void**)&o,   g_o);
    cudaGetSymbolAddress((void**)&scores, g_scores);

    bf16 *xh, *xl, *outh, *outl, *ath, *atl, *y0h, *y0l, *oh, *ol, *hh, *hl, *wh, *wl;
    bf16 *qkvh, *qkvl, *kv2h, *kv2l, *q2h, *q2l, *ph, *pl, *vth, *vtl;
    cudaGetSymbolAddress((void**)&xh,   g_xh);
    cudaGetSymbolAddress((void**)&xl,   g_xl);
    cudaGetSymbolAddress((void**)&outh, g_outh);
    cudaGetSymbolAddress((void**)&outl, g_outl);
    cudaGetSymbolAddress((void**)&ath,  g_ath);
    cudaGetSymbolAddress((void**)&atl,  g_atl);
    cudaGetSymbolAddress((void**)&y0h,  g_y0h);
    cudaGetSymbolAddress((void**)&y0l,  g_y0l);
    cudaGetSymbolAddress((void**)&oh,   g_oh);
    cudaGetSymbolAddress((void**)&ol,   g_ol);
    cudaGetSymbolAddress((void**)&hh,   g_hh);
    cudaGetSymbolAddress((void**)&hl,   g_hl);
    cudaGetSymbolAddress((void**)&wh,   g_wh);
    cudaGetSymbolAddress((void**)&wl,   g_wl);
    cudaGetSymbolAddress((void**)&qkvh, g_qkvh);
    cudaGetSymbolAddress((void**)&qkvl, g_qkvl);
    cudaGetSymbolAddress((void**)&kv2h, g_kv2h);
    cudaGetSymbolAddress((void**)&kv2l, g_kv2l);
    cudaGetSymbolAddress((void**)&q2h,  g_q2h);
    cudaGetSymbolAddress((void**)&q2l,  g_q2l);
    cudaGetSymbolAddress((void**)&ph,   g_ph);
    cudaGetSymbolAddress((void**)&pl,   g_pl);
    cudaGetSymbolAddress((void**)&vth,  g_vth);
    cudaGetSymbolAddress((void**)&vtl,  g_vtl);

    // ---- Weight conversion ----
    dim3 blk(32, 8);
    const int li = L_ - 1;
    wconv_kernel<<<dim3(16, 16, 6), blk>>>(eWq, wh + O_EQKV,          wl + O_EQKV,          D_, D_, 3 * DD);
    wconv_kernel<<<dim3(16, 16, 6), blk>>>(eWk, wh + O_EQKV + DD,     wl + O_EQKV + DD,     D_, D_, 3 * DD);
    wconv_kernel<<<dim3(16, 16, 6), blk>>>(eWv, wh + O_EQKV + 2 * DD, wl + O_EQKV + 2 * DD, D_, D_, 3 * DD);
    wconv_kernel<<<dim3(16, 16, 6), blk>>>(eWo, wh + O_EWO, wl + O_EWO, D_, D_, DD);
    wconv_kernel<<<dim3(64, 16, 6), blk>>>(eW1, wh + O_EW1, wl + O_EW1, D_, DFF_, DDF);
    wconv_kernel<<<dim3(16, 64, 6), blk>>>(eW2, wh + O_EW2, wl + O_EW2, DFF_, D_, DDF);
    wconv_kernel<<<dim3(16, 16, 1), blk>>>(dWq1 + (size_t)li * DDi, wh + O_DQKV1,          wl + O_DQKV1,          D_, D_, 3 * DD);
    wconv_kernel<<<dim3(16, 16, 1), blk>>>(dWk1 + (size_t)li * DDi, wh + O_DQKV1 + DD,     wl + O_DQKV1 + DD,     D_, D_, 3 * DD);
    wconv_kernel<<<dim3(16, 16, 1), blk>>>(dWv1 + (size_t)li * DDi, wh + O_DQKV1 + 2 * DD, wl + O_DQKV1 + 2 * DD, D_, D_, 3 * DD);
    wconv_kernel<<<dim3(16, 16, 1), blk>>>(dWo1 + (size_t)li * DDi, wh + O_DWO1, wl + O_DWO1, D_, D_, DD);
    wconv_kernel<<<dim3(16, 16, 1), blk>>>(dWq2 + (size_t)li * DDi, wh + O_DWQ2, wl + O_DWQ2, D_, D_, DD);
    wconv_kernel<<<dim3(16, 16, 1), blk>>>(dWk2 + (size_t)li * DDi, wh + O_DKV2,      wl + O_DKV2,      D_, D_, 2 * DD);
    wconv_kernel<<<dim3(16, 16, 1), blk>>>(dWv2 + (size_t)li * DDi, wh + O_DKV2 + DD, wl + O_DKV2 + DD, D_, D_, 2 * DD);
    wconv_kernel<<<dim3(16, 16, 1), blk>>>(dWo2 + (size_t)li * DDi, wh + O_DWO2, wl + O_DWO2, D_, D_, DD);
    wconv_kernel<<<dim3(64, 16, 1), blk>>>(dW1 + (size_t)li * (D_ * DFF_), wh + O_DW1, wl + O_DW1, D_, DFF_, DDF);
    wconv_kernel<<<dim3(16, 64, 1), blk>>>(dW2 + (size_t)li * (D_ * DFF_), wh + O_DW2, wl + O_DW2, DFF_, D_, DDF);
    wconv_kernel<<<dim3(1000, 16, 1), blk>>>(Wout, wh + O_WOUT, wl + O_WOUT, D_, V_, (uint64_t)D_ * V_);

    const dim3 vtGrid(16, 2, 32), qkGrid(4, 4, 32), smGrid(S_, 32), avGrid(1, 4, 32);
    const dim3 vtBlk(32, 8);

    // ---------------- Encoder ----------------
    embed_kernel<<<BS_, 128>>>(src, emb, x, xh, xl);
    for (int i = 0; i < L_; i++) {
        run_bgemm(4, xh, xl, wh + O_EQKV + (size_t)i * 3 * DD, wl + O_EQKV + (size_t)i * 3 * DD,
                  nullptr, nullptr, qkvh, qkvl, BS_, 3 * D_, D_);
        vt_kernel<<<vtGrid, vtBlk>>>(qkvh + 2 * D_, qkvl + 2 * D_, 3 * D_, vth, vtl);
        qk_gemm<<<qkGrid, 256, QK_SMEM>>>(qkvh, qkvl, 3 * D_,
                                          qkvh + D_, qkvl + D_, 3 * D_, scores);
        softmax_kernel<<<smGrid, 128>>>(scores, src, ph, pl, 0);
        av_gemm<<<avGrid, 256, AV_SMEM>>>(ph, pl, vth, vtl, ath, atl);
        run_bgemm(0, ath, atl, wh + O_EWO + (size_t)i * DD, wl + O_EWO + (size_t)i * DD,
                  nullptr, a, nullptr, nullptr, BS_, D_, D_);
        add_ln_kernel<<<BS_, 128>>>(x, a, out, outh, outl);
        run_bgemm(3, outh, outl, wh + O_EW1 + (size_t)i * DDF, wl + O_EW1 + (size_t)i * DDF,
                  eb1 + (size_t)i * DFF_, nullptr, hh, hl, BS_, DFF_, D_);
        run_bgemm(1, hh, hl, wh + O_EW2 + (size_t)i * DDF, wl + O_EW2 + (size_t)i * DDF,
                  eb2 + (size_t)i * D_, f, nullptr, nullptr, BS_, D_, DFF_);
        add_ln_kernel<<<BS_, 128>>>(a, f, x, xh, xl);
    }

    // ---------------- Decoder (last layer only) ----------------
    embed_kernel<<<BS_, 128>>>(tgt, emb, y0, y0h, y0l);
    {
        run_bgemm(4, y0h, y0l, wh + O_DQKV1, wl + O_DQKV1, nullptr, nullptr,
                  qkvh, qkvl, BS_, 3 * D_, D_);
        vt_kernel<<<vtGrid, vtBlk>>>(qkvh + 2 * D_, qkvl + 2 * D_, 3 * D_, vth, vtl);
        qk_gemm<<<qkGrid, 256, QK_SMEM>>>(qkvh, qkvl, 3 * D_,
                                          qkvh + D_, qkvl + D_, 3 * D_, scores);
        softmax_kernel<<<smGrid, 128>>>(scores, tgt, ph, pl, 1);
        av_gemm<<<avGrid, 256, AV_SMEM>>>(ph, pl, vth, vtl, ath, atl);
        run_bgemm(0, ath, atl, wh + O_DWO1, wl + O_DWO1, nullptr, a,
                  nullptr, nullptr, BS_, D_, D_);
        add_ln_kernel<<<BS_, 128>>>(y0, a, o, oh, ol);

        run_bgemm(4, oh, ol, wh + O_DWQ2, wl + O_DWQ2, nullptr, nullptr,
                  q2h, q2l, BS_, D_, D_);
        run_bgemm(4, xh, xl, wh + O_DKV2, wl + O_DKV2, nullptr, nullptr,
                  kv2h, kv2l, BS_, 2 * D_, D_);
        vt_kernel<<<vtGrid, vtBlk>>>(kv2h + D_, kv2l + D_, 2 * D_, vth, vtl);
        qk_gemm<<<qkGrid, 256, QK_SMEM>>>(q2h, q2l, D_, kv2h, kv2l, 2 * D_, scores);
        softmax_kernel<<<smGrid, 128>>>(scores, src, ph, pl, 0);
        av_gemm<<<avGrid, 256, AV_SMEM>>>(ph, pl, vth, vtl, ath, atl);
        run_bgemm(0, ath, atl, wh + O_DWO2, wl + O_DWO2, nullptr, a,
                  nullptr, nullptr, BS_, D_, D_);
        add_ln_kernel<<<BS_, 128>>>(o, a, o, oh, ol);

        run_bgemm(3, oh, ol, wh + O_DW1, wl + O_DW1, db1 + (size_t)li * DFF_,
                  nullptr, hh, hl, BS_, DFF_, D_);
        run_bgemm(1, hh, hl, wh + O_DW2, wl + O_DW2, db2 + (size_t)li * D_,
                  f, nullptr, nullptr, BS_, D_, DFF_);
        add_ln_kernel<<<BS_, 128>>>(o, f, o, oh, ol);
    }

    // ---------------- Logits ----------------
    run_bgemm(1, oh, ol, wh + O_WOUT, wl + O_WOUT, bout, (float*)d_out,
              nullptr, nullptr, BS_, V_, D_);
}